// round 2
// baseline (speedup 1.0000x reference)
#include <cuda_runtime.h>
#include <math.h>

#define TILE_E  64
#define DD      128
#define HH      256
#define KC      16
#define NTHREADS 256
#define EPSLN   1e-5f

__device__ __forceinline__ float warp_allreduce(float v) {
#pragma unroll
    for (int o = 16; o > 0; o >>= 1)
        v += __shfl_xor_sync(0xffffffffu, v, o);
    return v;
}

// Register-tiled GEMM: acc[8][8] += A(64 x K, smem) @ W^T (W is [HH][K] row-major, global)
// Thread (warp,lane) computes edges [warp*8, warp*8+8) x hidden {lane + jj*32}.
template <int K>
__device__ __forceinline__ void gemm_tile(const float (*__restrict__ A)[K],
                                          const float* __restrict__ W,
                                          float (*__restrict__ Bs)[HH + 1],
                                          float acc[8][8],
                                          int warp, int lane, int tid)
{
#pragma unroll 1
    for (int k0 = 0; k0 < K; k0 += KC) {
        // stage W chunk: Bs[kk][j] = W[j][k0+kk]
#pragma unroll
        for (int p = 0; p < (HH * KC) / NTHREADS; p++) {
            int l  = tid + p * NTHREADS;
            int kk = l & (KC - 1);
            int j  = l >> 4;
            Bs[kk][j] = W[(size_t)j * K + k0 + kk];
        }
        __syncthreads();

#pragma unroll
        for (int k4 = 0; k4 < KC; k4 += 4) {
            float4 a4[8];
#pragma unroll
            for (int ii = 0; ii < 8; ii++)
                a4[ii] = *(const float4*)&A[warp * 8 + ii][k0 + k4];
#pragma unroll
            for (int q = 0; q < 4; q++) {
                float bfrag[8];
#pragma unroll
                for (int jj = 0; jj < 8; jj++)
                    bfrag[jj] = Bs[k4 + q][lane + jj * 32];
#pragma unroll
                for (int ii = 0; ii < 8; ii++) {
                    float av = (q == 0) ? a4[ii].x : (q == 1) ? a4[ii].y
                             : (q == 2) ? a4[ii].z : a4[ii].w;
#pragma unroll
                    for (int jj = 0; jj < 8; jj++)
                        acc[ii][jj] = fmaf(av, bfrag[jj], acc[ii][jj]);
                }
            }
        }
        __syncthreads();
    }
}

__global__ void __launch_bounds__(NTHREADS, 1)
mlp_head_kernel(const float* __restrict__ h,
                const int* __restrict__ src,
                const int* __restrict__ dst,
                const float* __restrict__ W1, const float* __restrict__ b1,
                const float* __restrict__ g1, const float* __restrict__ be1,
                const float* __restrict__ W2, const float* __restrict__ b2,
                const float* __restrict__ g2, const float* __restrict__ be2,
                const float* __restrict__ W3, const float* __restrict__ b3,
                float* __restrict__ out, int E, int Nn)
{
    extern __shared__ float smem[];
    float (*xs)[DD]     = (float (*)[DD])smem;                                 // 64 x 128
    float (*yb)[HH]     = (float (*)[HH])(smem + TILE_E * DD);                 // 64 x 256
    float (*Bs)[HH + 1] = (float (*)[HH + 1])(smem + TILE_E * DD + TILE_E * HH); // 16 x 257

    const int tid  = threadIdx.x;
    const int lane = tid & 31;
    const int warp = tid >> 5;
    const int e0   = blockIdx.x * TILE_E;

    // ---- gather: xs[e][:] = h[src[e]] * h[dst[e]] (float4, L2-hit) ----
    {
        const int vec = lane;  // 32 float4 per 128-float row
#pragma unroll
        for (int ep = 0; ep < TILE_E; ep += 8) {
            int e  = ep + warp;
            int eg = e0 + e;
            int s = 0, d = 0;
            if (eg < E) { s = src[eg]; d = dst[eg]; }
            if ((unsigned)s >= (unsigned)Nn) s = 0;
            if ((unsigned)d >= (unsigned)Nn) d = 0;
            float4 a = ((const float4*)(h + (size_t)s * DD))[vec];
            float4 b = ((const float4*)(h + (size_t)d * DD))[vec];
            ((float4*)xs[e])[vec] = make_float4(a.x * b.x, a.y * b.y, a.z * b.z, a.w * b.w);
        }
    }
    __syncthreads();

    float acc[8][8];
#pragma unroll
    for (int ii = 0; ii < 8; ii++)
#pragma unroll
        for (int jj = 0; jj < 8; jj++) acc[ii][jj] = 0.f;

    // ---- layer 1: x @ W1^T ----
    gemm_tile<DD>(xs, W1, Bs, acc, warp, lane, tid);

    // ---- LN1 + ReLU (in registers, warp holds full 256-wide row) ----
    {
        float bw[8], gw[8], bt[8];
#pragma unroll
        for (int jj = 0; jj < 8; jj++) {
            int j = lane + jj * 32;
            bw[jj] = b1[j]; gw[jj] = g1[j]; bt[jj] = be1[j];
        }
#pragma unroll
        for (int ii = 0; ii < 8; ii++) {
            float v[8], s = 0.f;
#pragma unroll
            for (int jj = 0; jj < 8; jj++) { v[jj] = acc[ii][jj] + bw[jj]; s += v[jj]; }
            float mu = warp_allreduce(s) * (1.f / HH);
            float s2 = 0.f;
#pragma unroll
            for (int jj = 0; jj < 8; jj++) { float dv = v[jj] - mu; s2 += dv * dv; }
            float rs = rsqrtf(warp_allreduce(s2) * (1.f / HH) + EPSLN);
#pragma unroll
            for (int jj = 0; jj < 8; jj++) {
                float y = (v[jj] - mu) * rs * gw[jj] + bt[jj];
                yb[warp * 8 + ii][lane + jj * 32] = fmaxf(y, 0.f);
            }
        }
    }
    __syncthreads();

#pragma unroll
    for (int ii = 0; ii < 8; ii++)
#pragma unroll
        for (int jj = 0; jj < 8; jj++) acc[ii][jj] = 0.f;

    // ---- layer 2: y1 @ W2^T ----
    gemm_tile<HH>(yb, W2, Bs, acc, warp, lane, tid);

    // ---- LN2 + ReLU + final dot with W3 + sigmoid (never materialized) ----
    {
        float bw[8], gw[8], bt[8], w3v[8];
#pragma unroll
        for (int jj = 0; jj < 8; jj++) {
            int j = lane + jj * 32;
            bw[jj] = b2[j]; gw[jj] = g2[j]; bt[jj] = be2[j]; w3v[jj] = W3[j];
        }
        float b3s = b3[0];
#pragma unroll
        for (int ii = 0; ii < 8; ii++) {
            float v[8], s = 0.f;
#pragma unroll
            for (int jj = 0; jj < 8; jj++) { v[jj] = acc[ii][jj] + bw[jj]; s += v[jj]; }
            float mu = warp_allreduce(s) * (1.f / HH);
            float s2 = 0.f;
#pragma unroll
            for (int jj = 0; jj < 8; jj++) { float dv = v[jj] - mu; s2 += dv * dv; }
            float rs = rsqrtf(warp_allreduce(s2) * (1.f / HH) + EPSLN);
            float p = 0.f;
#pragma unroll
            for (int jj = 0; jj < 8; jj++) {
                float y = (v[jj] - mu) * rs * gw[jj] + bt[jj];
                y = fmaxf(y, 0.f);
                p = fmaf(y, w3v[jj], p);
            }
            p = warp_allreduce(p);
            if (lane == 0) {
                int eg = e0 + warp * 8 + ii;
                if (eg < E) out[eg] = 1.f / (1.f + expf(-(p + b3s)));
            }
        }
    }
}

extern "C" void kernel_launch(void* const* d_in, const int* in_sizes, int n_in,
                              void* d_out, int out_size)
{
    const float* h   = (const float*)d_in[0];
    const int*   src = (const int*)d_in[1];
    const int*   dst = (const int*)d_in[2];
    const float* W1 = (const float*)d_in[3];  const float* b1 = (const float*)d_in[4];
    const float* g1 = (const float*)d_in[5];  const float* be1 = (const float*)d_in[6];
    const float* W2 = (const float*)d_in[7];  const float* b2 = (const float*)d_in[8];
    const float* g2 = (const float*)d_in[9];  const float* be2 = (const float*)d_in[10];
    const float* W3 = (const float*)d_in[11]; const float* b3 = (const float*)d_in[12];

    int E  = in_sizes[1];          // element count of src
    int Nn = in_sizes[0] / DD;     // nodes

    int smem_bytes = (TILE_E * DD + TILE_E * HH + KC * (HH + 1)) * (int)sizeof(float);
    cudaFuncSetAttribute(mlp_head_kernel,
                         cudaFuncAttributeMaxDynamicSharedMemorySize, smem_bytes);

    int grid = (E + TILE_E - 1) / TILE_E;
    mlp_head_kernel<<<grid, NTHREADS, smem_bytes>>>(
        h, src, dst, W1, b1, g1, be1, W2, b2, g2, be2, W3, b3,
        (float*)d_out, E, Nn);
}

// round 4
// speedup vs baseline: 2.9079x; 2.9079x over previous
#include <cuda_runtime.h>
#include <cuda_bf16.h>
#include <math.h>
#include <stdint.h>

#define NTHR 256
#define TE   64
#define DD   128
#define HH   256
#define EPSLN 1e-5f

// ---------------- smem layout (byte offsets) ----------------
#define OFF_B1S   0
#define OFF_G1S   1024
#define OFF_BE1S  2048
#define OFF_B2S   3072
#define OFF_G2S   4096
#define OFF_BE2S  5120
#define OFF_W3S   6144
#define OFF_LNEX  7168      // 64 rows x 2 halves x float2 = 1024
#define OFF_PEX   8192      // 64 x 2 x float = 512
#define TILES     8704
// phase 1: A1 (64x128 bf16, row stride 136) hi/lo ; B1 blobs hi/lo
#define A1HI  (TILES)                 // 17408
#define A1LO  (TILES + 17408)
#define B1HI  (TILES + 34816)         // 65536
#define B1LO  (TILES + 100352)        // ends 165888
// phase 2 (alias): A2 (64x256 bf16, row stride 264) hi/lo ; B2 double buffer
#define A2HI  (TILES)                 // 33792
#define A2LO  (TILES + 33792)
#define B2BUF0 (TILES + 67584)        // 65536 (hi 32768 | lo 32768)
#define B2BUF1 (TILES + 133120)
#define SMEM_BYTES (TILES + 198656)   // 207360

// fragment-ordered weight blobs: slot = ((ntile*KSTEPS + kstep)*32 + lane) -> 8 bytes
// {W[n][k0],W[n][k0+1], W[n][k0+8],W[n][k0+9]}, n = ntile*8 + lane/4, k0 = kstep*16 + (lane%4)*2
__device__ __align__(16) unsigned char g_W1hi[65536];
__device__ __align__(16) unsigned char g_W1lo[65536];
// W2 blob: [kchunk 4][ntile 32][kstep 4][lane 32] x 8B
__device__ __align__(16) unsigned char g_W2hi[131072];
__device__ __align__(16) unsigned char g_W2lo[131072];

__device__ __forceinline__ void split_bf16(float x, uint16_t& hi, uint16_t& lo) {
    __nv_bfloat16 h = __float2bfloat16_rn(x);
    __nv_bfloat16 l = __float2bfloat16_rn(x - __bfloat162float(h));
    hi = __bfloat16_as_ushort(h);
    lo = __bfloat16_as_ushort(l);
}

__device__ __forceinline__ void mma_bf16(float d[4], const uint32_t a[4], const uint32_t b[2]) {
    asm volatile(
        "mma.sync.aligned.m16n8k16.row.col.f32.bf16.bf16.f32 "
        "{%0,%1,%2,%3}, {%4,%5,%6,%7}, {%8,%9}, {%0,%1,%2,%3};"
        : "+f"(d[0]), "+f"(d[1]), "+f"(d[2]), "+f"(d[3])
        : "r"(a[0]), "r"(a[1]), "r"(a[2]), "r"(a[3]), "r"(b[0]), "r"(b[1]));
}

__device__ __forceinline__ void cp16(uint32_t dst_smem, const void* gsrc) {
    asm volatile("cp.async.cg.shared.global [%0], [%1], 16;" :: "r"(dst_smem), "l"(gsrc));
}
#define CP_COMMIT() asm volatile("cp.async.commit_group;" ::: "memory")
#define CP_WAIT(N)  asm volatile("cp.async.wait_group %0;" :: "n"(N) : "memory")

// ---------------- prep: split + repack weights into fragment-ordered blobs ----------------
__global__ void prep_kernel(const float* __restrict__ W1, const float* __restrict__ W2) {
    int i = blockIdx.x * blockDim.x + threadIdx.x;
    if (i < 8192) {                                    // W1 [256n][128k], 32 nt x 8 ks
        int nt = i >> 8, ks = (i >> 5) & 7, lane = i & 31;
        int n = nt * 8 + (lane >> 2);
        int k0 = ks * 16 + (lane & 3) * 2;
        const float* w = W1 + n * 128 + k0;
        uint16_t h0,h1,h2,h3,l0,l1,l2,l3;
        split_bf16(w[0], h0, l0); split_bf16(w[1], h1, l1);
        split_bf16(w[8], h2, l2); split_bf16(w[9], h3, l3);
        ((uint2*)g_W1hi)[i] = make_uint2((uint32_t)h0 | ((uint32_t)h1 << 16),
                                         (uint32_t)h2 | ((uint32_t)h3 << 16));
        ((uint2*)g_W1lo)[i] = make_uint2((uint32_t)l0 | ((uint32_t)l1 << 16),
                                         (uint32_t)l2 | ((uint32_t)l3 << 16));
    } else if (i < 8192 + 16384) {                     // W2 [256n][256k], 4 kc x 32 nt x 4 ks
        int j = i - 8192;
        int kc = j >> 12, nt = (j >> 7) & 31, ks = (j >> 5) & 3, lane = j & 31;
        int n = nt * 8 + (lane >> 2);
        int k0 = kc * 64 + ks * 16 + (lane & 3) * 2;
        const float* w = W2 + n * 256 + k0;
        uint16_t h0,h1,h2,h3,l0,l1,l2,l3;
        split_bf16(w[0], h0, l0); split_bf16(w[1], h1, l1);
        split_bf16(w[8], h2, l2); split_bf16(w[9], h3, l3);
        ((uint2*)g_W2hi)[j] = make_uint2((uint32_t)h0 | ((uint32_t)h1 << 16),
                                         (uint32_t)h2 | ((uint32_t)h3 << 16));
        ((uint2*)g_W2lo)[j] = make_uint2((uint32_t)l0 | ((uint32_t)l1 << 16),
                                         (uint32_t)l2 | ((uint32_t)l3 << 16));
    }
}

// ---------------- main ----------------
__global__ void __launch_bounds__(NTHR, 1)
mlp_mma_kernel(const float* __restrict__ h,
               const int* __restrict__ src, const int* __restrict__ dst,
               const float* __restrict__ b1, const float* __restrict__ g1, const float* __restrict__ be1,
               const float* __restrict__ b2, const float* __restrict__ g2, const float* __restrict__ be2,
               const float* __restrict__ W3, const float* __restrict__ b3,
               float* __restrict__ out, int E, int Nn)
{
    extern __shared__ __align__(16) char smem[];
    const int tid   = threadIdx.x;
    const int wid   = tid >> 5;
    const int lane  = tid & 31;
    const int rowt  = wid & 3;          // row tile: rows [rowt*16, rowt*16+16)
    const int nhalf = wid >> 2;         // N half: cols [nhalf*128, nhalf*128+128)
    const int e0    = blockIdx.x * TE;

    // --- async-stage B1 blobs (131072 B) ---
    {
        uint32_t dh = (uint32_t)__cvta_generic_to_shared(smem + B1HI);
        uint32_t dl = (uint32_t)__cvta_generic_to_shared(smem + B1LO);
#pragma unroll
        for (int i = 0; i < 16; i++) {
            cp16(dh + (tid + i * NTHR) * 16, (const char*)g_W1hi + (tid + i * NTHR) * 16);
            cp16(dl + (tid + i * NTHR) * 16, (const char*)g_W1lo + (tid + i * NTHR) * 16);
        }
        CP_COMMIT();
    }

    // --- params ---
    ((float*)(smem + OFF_B1S))[tid]  = b1[tid];
    ((float*)(smem + OFF_G1S))[tid]  = g1[tid];
    ((float*)(smem + OFF_BE1S))[tid] = be1[tid];
    ((float*)(smem + OFF_B2S))[tid]  = b2[tid];
    ((float*)(smem + OFF_G2S))[tid]  = g2[tid];
    ((float*)(smem + OFF_BE2S))[tid] = be2[tid];
    ((float*)(smem + OFF_W3S))[tid]  = W3[tid];

    // --- gather x = h[src]*h[dst], split to bf16 hi/lo, A1 row-major (stride 68 words) ---
    {
        int row = tid >> 2, q = tid & 3;
        int eg = e0 + row;
        int si = 0, di = 0;
        if (eg < E) { si = src[eg]; di = dst[eg]; }
        if ((unsigned)si >= (unsigned)Nn) si = 0;
        if ((unsigned)di >= (unsigned)Nn) di = 0;
        const float4* ps = (const float4*)(h + (size_t)si * DD) + q * 8;
        const float4* pd = (const float4*)(h + (size_t)di * DD) + q * 8;
        uint32_t* oh = (uint32_t*)(smem + A1HI) + row * 68 + q * 16;
        uint32_t* ol = (uint32_t*)(smem + A1LO) + row * 68 + q * 16;
#pragma unroll
        for (int i = 0; i < 8; i++) {
            float4 a = ps[i], b = pd[i];
            uint16_t h0,h1,h2,h3,l0,l1,l2,l3;
            split_bf16(a.x * b.x, h0, l0); split_bf16(a.y * b.y, h1, l1);
            split_bf16(a.z * b.z, h2, l2); split_bf16(a.w * b.w, h3, l3);
            oh[i * 2]     = (uint32_t)h0 | ((uint32_t)h1 << 16);
            oh[i * 2 + 1] = (uint32_t)h2 | ((uint32_t)h3 << 16);
            ol[i * 2]     = (uint32_t)l0 | ((uint32_t)l1 << 16);
            ol[i * 2 + 1] = (uint32_t)l2 | ((uint32_t)l3 << 16);
        }
    }
    CP_WAIT(0);
    __syncthreads();

    float acc[16][4];
#pragma unroll
    for (int t = 0; t < 16; t++) { acc[t][0]=acc[t][1]=acc[t][2]=acc[t][3]=0.f; }

    // ---- layer 1: K=128, 8 ksteps, 3-term split ----
    {
        const uint32_t* Ah = (const uint32_t*)(smem + A1HI);
        const uint32_t* Al = (const uint32_t*)(smem + A1LO);
        const int r  = rowt * 16 + (lane >> 2);
#pragma unroll 1
        for (int ks = 0; ks < 8; ks++) {
            int kp = ks * 8 + (lane & 3);
            uint32_t ah[4], al[4];
            ah[0] = Ah[r * 68 + kp];       ah[1] = Ah[(r + 8) * 68 + kp];
            ah[2] = Ah[r * 68 + kp + 4];   ah[3] = Ah[(r + 8) * 68 + kp + 4];
            al[0] = Al[r * 68 + kp];       al[1] = Al[(r + 8) * 68 + kp];
            al[2] = Al[r * 68 + kp + 4];   al[3] = Al[(r + 8) * 68 + kp + 4];
#pragma unroll
            for (int tl = 0; tl < 16; tl++) {
                int nt = nhalf * 16 + tl;
                uint2 bh = *(const uint2*)(smem + B1HI + (size_t)((nt * 8 + ks) * 32 + lane) * 8);
                uint2 bl = *(const uint2*)(smem + B1LO + (size_t)((nt * 8 + ks) * 32 + lane) * 8);
                mma_bf16(acc[tl], ah, (const uint32_t*)&bh);
                mma_bf16(acc[tl], ah, (const uint32_t*)&bl);
                mma_bf16(acc[tl], al, (const uint32_t*)&bh);
            }
        }
    }

    // ---- epilogue 1: bias, LN stats ----
    const int r0 = rowt * 16 + (lane >> 2);
    const int r1 = r0 + 8;
    const float* b1s  = (const float*)(smem + OFF_B1S);
    const float* g1s  = (const float*)(smem + OFF_G1S);
    const float* be1s = (const float*)(smem + OFF_BE1S);
    float2* lnex = (float2*)(smem + OFF_LNEX);
    {
        float sa = 0.f, s2a = 0.f, sb = 0.f, s2b = 0.f;
#pragma unroll
        for (int tl = 0; tl < 16; tl++) {
            int c0 = nhalf * 128 + tl * 8 + (lane & 3) * 2;
            acc[tl][0] += b1s[c0]; acc[tl][1] += b1s[c0 + 1];
            acc[tl][2] += b1s[c0]; acc[tl][3] += b1s[c0 + 1];
            sa += acc[tl][0] + acc[tl][1]; s2a += acc[tl][0]*acc[tl][0] + acc[tl][1]*acc[tl][1];
            sb += acc[tl][2] + acc[tl][3]; s2b += acc[tl][2]*acc[tl][2] + acc[tl][3]*acc[tl][3];
        }
#pragma unroll
        for (int o = 1; o <= 2; o <<= 1) {
            sa += __shfl_xor_sync(0xffffffffu, sa, o);  s2a += __shfl_xor_sync(0xffffffffu, s2a, o);
            sb += __shfl_xor_sync(0xffffffffu, sb, o);  s2b += __shfl_xor_sync(0xffffffffu, s2b, o);
        }
        if ((lane & 3) == 0) {
            lnex[r0 * 2 + nhalf] = make_float2(sa, s2a);
            lnex[r1 * 2 + nhalf] = make_float2(sb, s2b);
        }
    }
    __syncthreads();   // layer-1 mma + stats done everywhere; B1/A1 now dead

    // prefetch W2 chunk 0 into buf0 (region was B1)
    {
        uint32_t d0 = (uint32_t)__cvta_generic_to_shared(smem + B2BUF0);
#pragma unroll
        for (int i = 0; i < 8; i++) {
            cp16(d0 + (tid + i * NTHR) * 16,           (const char*)g_W2hi + (tid + i * NTHR) * 16);
            cp16(d0 + 32768 + (tid + i * NTHR) * 16,   (const char*)g_W2lo + (tid + i * NTHR) * 16);
        }
        CP_COMMIT();
    }

    // ---- LN1 transform + ReLU + split -> A2 (stride 132 words) ----
    {
        float2 a0 = lnex[r0 * 2 + 0], a1 = lnex[r0 * 2 + 1];
        float2 b0 = lnex[r1 * 2 + 0], b1v = lnex[r1 * 2 + 1];
        float mua = (a0.x + a1.x) * (1.f / HH);
        float rsa = rsqrtf((a0.y + a1.y) * (1.f / HH) - mua * mua + EPSLN);
        float mub = (b0.x + b1v.x) * (1.f / HH);
        float rsb = rsqrtf((b0.y + b1v.y) * (1.f / HH) - mub * mub + EPSLN);
        uint32_t* A2h = (uint32_t*)(smem + A2HI);
        uint32_t* A2l = (uint32_t*)(smem + A2LO);
#pragma unroll
        for (int tl = 0; tl < 16; tl++) {
            int c0 = nhalf * 128 + tl * 8 + (lane & 3) * 2;
            float ga = g1s[c0], gb = g1s[c0 + 1], ba = be1s[c0], bb = be1s[c0 + 1];
            float y00 = fmaxf((acc[tl][0] - mua) * rsa * ga + ba, 0.f);
            float y01 = fmaxf((acc[tl][1] - mua) * rsa * gb + bb, 0.f);
            float y10 = fmaxf((acc[tl][2] - mub) * rsb * ga + ba, 0.f);
            float y11 = fmaxf((acc[tl][3] - mub) * rsb * gb + bb, 0.f);
            uint16_t h0,h1,l0,l1;
            int w = c0 >> 1;
            split_bf16(y00, h0, l0); split_bf16(y01, h1, l1);
            A2h[r0 * 132 + w] = (uint32_t)h0 | ((uint32_t)h1 << 16);
            A2l[r0 * 132 + w] = (uint32_t)l0 | ((uint32_t)l1 << 16);
            split_bf16(y10, h0, l0); split_bf16(y11, h1, l1);
            A2h[r1 * 132 + w] = (uint32_t)h0 | ((uint32_t)h1 << 16);
            A2l[r1 * 132 + w] = (uint32_t)l0 | ((uint32_t)l1 << 16);
        }
    }

#pragma unroll
    for (int t = 0; t < 16; t++) { acc[t][0]=acc[t][1]=acc[t][2]=acc[t][3]=0.f; }

    // ---- layer 2: K=256 in 4 chunks of 64, double-buffered cp.async ----
    {
        const uint32_t* Ah = (const uint32_t*)(smem + A2HI);
        const uint32_t* Al = (const uint32_t*)(smem + A2LO);
        const int r = r0;
#pragma unroll 1
        for (int kc = 0; kc < 4; kc++) {
            if (kc < 3) {
                uint32_t d = (uint32_t)__cvta_generic_to_shared(
                    smem + ((kc & 1) ? B2BUF0 : B2BUF1));   // (kc+1)&1 buffer
                const char* sh = (const char*)g_W2hi + (kc + 1) * 32768;
                const char* sl = (const char*)g_W2lo + (kc + 1) * 32768;
#pragma unroll
                for (int i = 0; i < 8; i++) {
                    cp16(d + (tid + i * NTHR) * 16,         sh + (tid + i * NTHR) * 16);
                    cp16(d + 32768 + (tid + i * NTHR) * 16, sl + (tid + i * NTHR) * 16);
                }
                CP_COMMIT();
                CP_WAIT(1);
            } else {
                CP_WAIT(0);
            }
            __syncthreads();
            const char* buf = smem + ((kc & 1) ? B2BUF1 : B2BUF0);
#pragma unroll
            for (int ks = 0; ks < 4; ks++) {
                int kp = kc * 32 + ks * 8 + (lane & 3);
                uint32_t ah[4], al[4];
                ah[0] = Ah[r * 132 + kp];      ah[1] = Ah[(r + 8) * 132 + kp];
                ah[2] = Ah[r * 132 + kp + 4];  ah[3] = Ah[(r + 8) * 132 + kp + 4];
                al[0] = Al[r * 132 + kp];      al[1] = Al[(r + 8) * 132 + kp];
                al[2] = Al[r * 132 + kp + 4];  al[3] = Al[(r + 8) * 132 + kp + 4];
#pragma unroll
                for (int tl = 0; tl < 16; tl++) {
                    int nt = nhalf * 16 + tl;
                    uint2 bh = *(const uint2*)(buf + (size_t)((nt * 4 + ks) * 32 + lane) * 8);
                    uint2 bl = *(const uint2*)(buf + 32768 + (size_t)((nt * 4 + ks) * 32 + lane) * 8);
                    mma_bf16(acc[tl], ah, (const uint32_t*)&bh);
                    mma_bf16(acc[tl], ah, (const uint32_t*)&bl);
                    mma_bf16(acc[tl], al, (const uint32_t*)&bh);
                }
            }
            __syncthreads();   // all reads of this buffer done before it is overwritten
        }
    }

    // ---- epilogue 2: bias, LN2, ReLU, dot W3, sigmoid ----
    const float* b2s  = (const float*)(smem + OFF_B2S);
    const float* g2s  = (const float*)(smem + OFF_G2S);
    const float* be2s = (const float*)(smem + OFF_BE2S);
    const float* w3s  = (const float*)(smem + OFF_W3S);
    {
        float sa = 0.f, s2a = 0.f, sb = 0.f, s2b = 0.f;
#pragma unroll
        for (int tl = 0; tl < 16; tl++) {
            int c0 = nhalf * 128 + tl * 8 + (lane & 3) * 2;
            acc[tl][0] += b2s[c0]; acc[tl][1] += b2s[c0 + 1];
            acc[tl][2] += b2s[c0]; acc[tl][3] += b2s[c0 + 1];
            sa += acc[tl][0] + acc[tl][1]; s2a += acc[tl][0]*acc[tl][0] + acc[tl][1]*acc[tl][1];
            sb += acc[tl][2] + acc[tl][3]; s2b += acc[tl][2]*acc[tl][2] + acc[tl][3]*acc[tl][3];
        }
#pragma unroll
        for (int o = 1; o <= 2; o <<= 1) {
            sa += __shfl_xor_sync(0xffffffffu, sa, o);  s2a += __shfl_xor_sync(0xffffffffu, s2a, o);
            sb += __shfl_xor_sync(0xffffffffu, sb, o);  s2b += __shfl_xor_sync(0xffffffffu, s2b, o);
        }
        if ((lane & 3) == 0) {
            lnex[r0 * 2 + nhalf] = make_float2(sa, s2a);
            lnex[r1 * 2 + nhalf] = make_float2(sb, s2b);
        }
    }
    __syncthreads();
    {
        float2 a0 = lnex[r0 * 2 + 0], a1 = lnex[r0 * 2 + 1];
        float2 b0 = lnex[r1 * 2 + 0], b1v = lnex[r1 * 2 + 1];
        float mua = (a0.x + a1.x) * (1.f / HH);
        float rsa = rsqrtf((a0.y + a1.y) * (1.f / HH) - mua * mua + EPSLN);
        float mub = (b0.x + b1v.x) * (1.f / HH);
        float rsb = rsqrtf((b0.y + b1v.y) * (1.f / HH) - mub * mub + EPSLN);
        float pa = 0.f, pb = 0.f;
#pragma unroll
        for (int tl = 0; tl < 16; tl++) {
            int c0 = nhalf * 128 + tl * 8 + (lane & 3) * 2;
            float ga = g2s[c0], gb = g2s[c0 + 1], ba = be2s[c0], bb = be2s[c0 + 1];
            float w0 = w3s[c0], w1 = w3s[c0 + 1];
            pa = fmaf(fmaxf((acc[tl][0] - mua) * rsa * ga + ba, 0.f), w0, pa);
            pa = fmaf(fmaxf((acc[tl][1] - mua) * rsa * gb + bb, 0.f), w1, pa);
            pb = fmaf(fmaxf((acc[tl][2] - mub) * rsb * ga + ba, 0.f), w0, pb);
            pb = fmaf(fmaxf((acc[tl][3] - mub) * rsb * gb + bb, 0.f), w1, pb);
        }
#pragma unroll
        for (int o = 1; o <= 2; o <<= 1) {
            pa += __shfl_xor_sync(0xffffffffu, pa, o);
            pb += __shfl_xor_sync(0xffffffffu, pb, o);
        }
        float* pex = (float*)(smem + OFF_PEX);
        if ((lane & 3) == 0) {
            pex[r0 * 2 + nhalf] = pa;
            pex[r1 * 2 + nhalf] = pb;
        }
    }
    __syncthreads();
    if (tid < TE) {
        float* pex = (float*)(smem + OFF_PEX);
        float p = pex[tid * 2] + pex[tid * 2 + 1] + b3[0];
        int eg = e0 + tid;
        if (eg < E) out[eg] = 1.f / (1.f + expf(-p));
    }
}

extern "C" void kernel_launch(void* const* d_in, const int* in_sizes, int n_in,
                              void* d_out, int out_size)
{
    const float* h   = (const float*)d_in[0];
    const int*   src = (const int*)d_in[1];
    const int*   dst = (const int*)d_in[2];
    const float* W1 = (const float*)d_in[3];  const float* b1 = (const float*)d_in[4];
    const float* g1 = (const float*)d_in[5];  const float* be1 = (const float*)d_in[6];
    const float* W2 = (const float*)d_in[7];  const float* b2 = (const float*)d_in[8];
    const float* g2 = (const float*)d_in[9];  const float* be2 = (const float*)d_in[10];
    const float* W3 = (const float*)d_in[11]; const float* b3 = (const float*)d_in[12];

    int E  = in_sizes[1];
    int Nn = in_sizes[0] / DD;

    prep_kernel<<<(8192 + 16384 + NTHR - 1) / NTHR, NTHR>>>(W1, W2);

    cudaFuncSetAttribute(mlp_mma_kernel,
                         cudaFuncAttributeMaxDynamicSharedMemorySize, SMEM_BYTES);
    int grid = (E + TE - 1) / TE;
    mlp_mma_kernel<<<grid, NTHR, SMEM_BYTES>>>(
        h, src, dst, b1, g1, be1, b2, g2, be2, W3, b3,
        (float*)d_out, E, Nn);
}

// round 5
// speedup vs baseline: 3.1596x; 1.0866x over previous
#include <cuda_runtime.h>
#include <cuda_bf16.h>
#include <math.h>
#include <stdint.h>

#define NTHR 512
#define TE   128
#define DD   128
#define HH   256
#define EPSLN 1e-5f

// ---------------- smem layout (byte offsets) ----------------
#define OFF_B1S   0
#define OFF_G1S   1024
#define OFF_BE1S  2048
#define OFF_B2S   3072
#define OFF_G2S   4096
#define OFF_BE2S  5120
#define OFF_W3S   6144
#define OFF_LNEX  7168      // 128 rows x 2 halves x float2 = 2048
#define OFF_PEX   9216      // 128 x 2 x float = 1024
#define TILES     10240
// phase 1: A1 (128x128 bf16, row stride 68 words) hi/lo ; B1 blobs hi/lo
#define A1HI  (TILES)                  // 34816
#define A1LO  (TILES + 34816)
#define B1HI  (TILES + 69632)          // 65536
#define B1LO  (TILES + 135168)         // ends TILES+200704
// phase 2 (alias): A2 (128x256 bf16, row stride 132 words) hi/lo ; B2 double buffer
#define A2HI   (TILES)                 // 67584
#define A2LO   (TILES + 67584)
#define B2BUF0 (TILES + 135168)        // 32768 each (hi 16384 | lo 16384)
#define B2BUF1 (TILES + 167936)
#define SMEM_BYTES (TILES + 200704)    // 210944

// fragment-ordered weight blobs:
// W1 blob slot = ((ntile*8 + kstep)*32 + lane) -> 8 bytes
//   {W[n][k0],W[n][k0+1], W[n][k0+8],W[n][k0+9]}, n = ntile*8 + lane/4, k0 = kstep*16 + (lane%4)*2
__device__ __align__(16) unsigned char g_W1hi[65536];
__device__ __align__(16) unsigned char g_W1lo[65536];
// W2 blob: [kchunk 8][ntile 32][kstep 2][lane 32] x 8B   (chunk = K 32)
__device__ __align__(16) unsigned char g_W2hi[131072];
__device__ __align__(16) unsigned char g_W2lo[131072];

__device__ __forceinline__ void split_bf16(float x, uint16_t& hi, uint16_t& lo) {
    __nv_bfloat16 h = __float2bfloat16_rn(x);
    __nv_bfloat16 l = __float2bfloat16_rn(x - __bfloat162float(h));
    hi = __bfloat16_as_ushort(h);
    lo = __bfloat16_as_ushort(l);
}

__device__ __forceinline__ void mma_bf16(float d[4], const uint32_t a[4], const uint32_t b[2]) {
    asm volatile(
        "mma.sync.aligned.m16n8k16.row.col.f32.bf16.bf16.f32 "
        "{%0,%1,%2,%3}, {%4,%5,%6,%7}, {%8,%9}, {%0,%1,%2,%3};"
        : "+f"(d[0]), "+f"(d[1]), "+f"(d[2]), "+f"(d[3])
        : "r"(a[0]), "r"(a[1]), "r"(a[2]), "r"(a[3]), "r"(b[0]), "r"(b[1]));
}

__device__ __forceinline__ void cp16(uint32_t dst_smem, const void* gsrc) {
    asm volatile("cp.async.cg.shared.global [%0], [%1], 16;" :: "r"(dst_smem), "l"(gsrc));
}
#define CP_COMMIT() asm volatile("cp.async.commit_group;" ::: "memory")
#define CP_WAIT(N)  asm volatile("cp.async.wait_group %0;" :: "n"(N) : "memory")

// ---------------- prep: split + repack weights into fragment-ordered blobs ----------------
__global__ void prep_kernel(const float* __restrict__ W1, const float* __restrict__ W2) {
    int i = blockIdx.x * blockDim.x + threadIdx.x;
    if (i < 8192) {                                    // W1 [256n][128k], 32 nt x 8 ks
        int nt = i >> 8, ks = (i >> 5) & 7, lane = i & 31;
        int n = nt * 8 + (lane >> 2);
        int k0 = ks * 16 + (lane & 3) * 2;
        const float* w = W1 + n * 128 + k0;
        uint16_t h0,h1,h2,h3,l0,l1,l2,l3;
        split_bf16(w[0], h0, l0); split_bf16(w[1], h1, l1);
        split_bf16(w[8], h2, l2); split_bf16(w[9], h3, l3);
        ((uint2*)g_W1hi)[i] = make_uint2((uint32_t)h0 | ((uint32_t)h1 << 16),
                                         (uint32_t)h2 | ((uint32_t)h3 << 16));
        ((uint2*)g_W1lo)[i] = make_uint2((uint32_t)l0 | ((uint32_t)l1 << 16),
                                         (uint32_t)l2 | ((uint32_t)l3 << 16));
    } else if (i < 8192 + 16384) {                     // W2 [256n][256k], 8 kc x 32 nt x 2 ks
        int j = i - 8192;
        int kc = j >> 11, nt = (j >> 6) & 31, ks = (j >> 5) & 1, lane = j & 31;
        int n = nt * 8 + (lane >> 2);
        int k0 = kc * 32 + ks * 16 + (lane & 3) * 2;
        const float* w = W2 + n * 256 + k0;
        uint16_t h0,h1,h2,h3,l0,l1,l2,l3;
        split_bf16(w[0], h0, l0); split_bf16(w[1], h1, l1);
        split_bf16(w[8], h2, l2); split_bf16(w[9], h3, l3);
        ((uint2*)g_W2hi)[j] = make_uint2((uint32_t)h0 | ((uint32_t)h1 << 16),
                                         (uint32_t)h2 | ((uint32_t)h3 << 16));
        ((uint2*)g_W2lo)[j] = make_uint2((uint32_t)l0 | ((uint32_t)l1 << 16),
                                         (uint32_t)l2 | ((uint32_t)l3 << 16));
    }
}

// ---------------- main ----------------
__global__ void __launch_bounds__(NTHR, 1)
mlp_mma_kernel(const float* __restrict__ h,
               const int* __restrict__ src, const int* __restrict__ dst,
               const float* __restrict__ b1, const float* __restrict__ g1, const float* __restrict__ be1,
               const float* __restrict__ b2, const float* __restrict__ g2, const float* __restrict__ be2,
               const float* __restrict__ W3, const float* __restrict__ b3,
               float* __restrict__ out, int E, int Nn)
{
    extern __shared__ __align__(16) char smem[];
    const int tid   = threadIdx.x;
    const int wid   = tid >> 5;
    const int lane  = tid & 31;
    const int rowt  = wid & 7;          // row tile: rows [rowt*16, rowt*16+16)
    const int nhalf = wid >> 3;         // N half: cols [nhalf*128, nhalf*128+128)
    const int e0    = blockIdx.x * TE;

    // --- async-stage B1 blobs (131072 B) ---
    {
        uint32_t dh = (uint32_t)__cvta_generic_to_shared(smem + B1HI);
        uint32_t dl = (uint32_t)__cvta_generic_to_shared(smem + B1LO);
#pragma unroll
        for (int i = 0; i < 8; i++) {
            cp16(dh + (tid + i * NTHR) * 16, (const char*)g_W1hi + (tid + i * NTHR) * 16);
            cp16(dl + (tid + i * NTHR) * 16, (const char*)g_W1lo + (tid + i * NTHR) * 16);
        }
        CP_COMMIT();
    }

    // --- params ---
    if (tid < HH) {
        ((float*)(smem + OFF_B1S))[tid]  = b1[tid];
        ((float*)(smem + OFF_G1S))[tid]  = g1[tid];
        ((float*)(smem + OFF_BE1S))[tid] = be1[tid];
        ((float*)(smem + OFF_B2S))[tid]  = b2[tid];
        ((float*)(smem + OFF_G2S))[tid]  = g2[tid];
        ((float*)(smem + OFF_BE2S))[tid] = be2[tid];
        ((float*)(smem + OFF_W3S))[tid]  = W3[tid];
    }

    // --- gather x = h[src]*h[dst], split to bf16 hi/lo, A1 row-major (stride 68 words) ---
    {
        int row = tid >> 2, q = tid & 3;
        int eg = e0 + row;
        int si = 0, di = 0;
        if (eg < E) { si = src[eg]; di = dst[eg]; }
        if ((unsigned)si >= (unsigned)Nn) si = 0;
        if ((unsigned)di >= (unsigned)Nn) di = 0;
        const float4* ps = (const float4*)(h + (size_t)si * DD) + q * 8;
        const float4* pd = (const float4*)(h + (size_t)di * DD) + q * 8;
        uint32_t* oh = (uint32_t*)(smem + A1HI) + row * 68 + q * 16;
        uint32_t* ol = (uint32_t*)(smem + A1LO) + row * 68 + q * 16;
#pragma unroll
        for (int i = 0; i < 8; i++) {
            float4 a = ps[i], b = pd[i];
            uint16_t h0,h1,h2,h3,l0,l1,l2,l3;
            split_bf16(a.x * b.x, h0, l0); split_bf16(a.y * b.y, h1, l1);
            split_bf16(a.z * b.z, h2, l2); split_bf16(a.w * b.w, h3, l3);
            oh[i * 2]     = (uint32_t)h0 | ((uint32_t)h1 << 16);
            oh[i * 2 + 1] = (uint32_t)h2 | ((uint32_t)h3 << 16);
            ol[i * 2]     = (uint32_t)l0 | ((uint32_t)l1 << 16);
            ol[i * 2 + 1] = (uint32_t)l2 | ((uint32_t)l3 << 16);
        }
    }
    CP_WAIT(0);
    __syncthreads();

    float acc[16][4];
#pragma unroll
    for (int t = 0; t < 16; t++) { acc[t][0]=acc[t][1]=acc[t][2]=acc[t][3]=0.f; }

    // ---- layer 1: K=128, 8 ksteps, 3-term split ----
    {
        const uint32_t* Ah = (const uint32_t*)(smem + A1HI);
        const uint32_t* Al = (const uint32_t*)(smem + A1LO);
        const int r = rowt * 16 + (lane >> 2);
#pragma unroll 1
        for (int ks = 0; ks < 8; ks++) {
            int kp = ks * 8 + (lane & 3);
            uint32_t ah[4], al[4];
            ah[0] = Ah[r * 68 + kp];       ah[1] = Ah[(r + 8) * 68 + kp];
            ah[2] = Ah[r * 68 + kp + 4];   ah[3] = Ah[(r + 8) * 68 + kp + 4];
            al[0] = Al[r * 68 + kp];       al[1] = Al[(r + 8) * 68 + kp];
            al[2] = Al[r * 68 + kp + 4];   al[3] = Al[(r + 8) * 68 + kp + 4];
#pragma unroll
            for (int tl = 0; tl < 16; tl++) {
                int nt = nhalf * 16 + tl;
                uint2 bh = *(const uint2*)(smem + B1HI + (size_t)((nt * 8 + ks) * 32 + lane) * 8);
                uint2 bl = *(const uint2*)(smem + B1LO + (size_t)((nt * 8 + ks) * 32 + lane) * 8);
                mma_bf16(acc[tl], ah, (const uint32_t*)&bh);
                mma_bf16(acc[tl], ah, (const uint32_t*)&bl);
                mma_bf16(acc[tl], al, (const uint32_t*)&bh);
            }
        }
    }

    // ---- epilogue 1: bias, LN stats ----
    const int r0 = rowt * 16 + (lane >> 2);
    const int r1 = r0 + 8;
    const float* b1s  = (const float*)(smem + OFF_B1S);
    const float* g1s  = (const float*)(smem + OFF_G1S);
    const float* be1s = (const float*)(smem + OFF_BE1S);
    float2* lnex = (float2*)(smem + OFF_LNEX);
    {
        float sa = 0.f, s2a = 0.f, sb = 0.f, s2b = 0.f;
#pragma unroll
        for (int tl = 0; tl < 16; tl++) {
            int c0 = nhalf * 128 + tl * 8 + (lane & 3) * 2;
            acc[tl][0] += b1s[c0]; acc[tl][1] += b1s[c0 + 1];
            acc[tl][2] += b1s[c0]; acc[tl][3] += b1s[c0 + 1];
            sa += acc[tl][0] + acc[tl][1]; s2a += acc[tl][0]*acc[tl][0] + acc[tl][1]*acc[tl][1];
            sb += acc[tl][2] + acc[tl][3]; s2b += acc[tl][2]*acc[tl][2] + acc[tl][3]*acc[tl][3];
        }
#pragma unroll
        for (int o = 1; o <= 2; o <<= 1) {
            sa += __shfl_xor_sync(0xffffffffu, sa, o);  s2a += __shfl_xor_sync(0xffffffffu, s2a, o);
            sb += __shfl_xor_sync(0xffffffffu, sb, o);  s2b += __shfl_xor_sync(0xffffffffu, s2b, o);
        }
        if ((lane & 3) == 0) {
            lnex[r0 * 2 + nhalf] = make_float2(sa, s2a);
            lnex[r1 * 2 + nhalf] = make_float2(sb, s2b);
        }
    }
    __syncthreads();   // layer-1 mma + stats done everywhere; A1/B1 now dead

    // prefetch W2 chunk 0 into buf0 (region was B1LO)
    {
        uint32_t d0 = (uint32_t)__cvta_generic_to_shared(smem + B2BUF0);
#pragma unroll
        for (int i = 0; i < 2; i++) {
            cp16(d0 + (tid + i * NTHR) * 16,           (const char*)g_W2hi + (tid + i * NTHR) * 16);
            cp16(d0 + 16384 + (tid + i * NTHR) * 16,   (const char*)g_W2lo + (tid + i * NTHR) * 16);
        }
        CP_COMMIT();
    }

    // ---- LN1 transform + ReLU + split -> A2 (stride 132 words) ----
    {
        float2 a0 = lnex[r0 * 2 + 0], a1 = lnex[r0 * 2 + 1];
        float2 b0 = lnex[r1 * 2 + 0], b1v = lnex[r1 * 2 + 1];
        float mua = (a0.x + a1.x) * (1.f / HH);
        float rsa = rsqrtf((a0.y + a1.y) * (1.f / HH) - mua * mua + EPSLN);
        float mub = (b0.x + b1v.x) * (1.f / HH);
        float rsb = rsqrtf((b0.y + b1v.y) * (1.f / HH) - mub * mub + EPSLN);
        uint32_t* A2h = (uint32_t*)(smem + A2HI);
        uint32_t* A2l = (uint32_t*)(smem + A2LO);
#pragma unroll
        for (int tl = 0; tl < 16; tl++) {
            int c0 = nhalf * 128 + tl * 8 + (lane & 3) * 2;
            float ga = g1s[c0], gb = g1s[c0 + 1], ba = be1s[c0], bb = be1s[c0 + 1];
            float y00 = fmaxf((acc[tl][0] - mua) * rsa * ga + ba, 0.f);
            float y01 = fmaxf((acc[tl][1] - mua) * rsa * gb + bb, 0.f);
            float y10 = fmaxf((acc[tl][2] - mub) * rsb * ga + ba, 0.f);
            float y11 = fmaxf((acc[tl][3] - mub) * rsb * gb + bb, 0.f);
            uint16_t h0,h1,l0,l1;
            int w = c0 >> 1;
            split_bf16(y00, h0, l0); split_bf16(y01, h1, l1);
            A2h[r0 * 132 + w] = (uint32_t)h0 | ((uint32_t)h1 << 16);
            A2l[r0 * 132 + w] = (uint32_t)l0 | ((uint32_t)l1 << 16);
            split_bf16(y10, h0, l0); split_bf16(y11, h1, l1);
            A2h[r1 * 132 + w] = (uint32_t)h0 | ((uint32_t)h1 << 16);
            A2l[r1 * 132 + w] = (uint32_t)l0 | ((uint32_t)l1 << 16);
        }
    }

#pragma unroll
    for (int t = 0; t < 16; t++) { acc[t][0]=acc[t][1]=acc[t][2]=acc[t][3]=0.f; }

    // ---- layer 2: K=256 in 8 chunks of 32, double-buffered cp.async ----
    {
        const uint32_t* Ah = (const uint32_t*)(smem + A2HI);
        const uint32_t* Al = (const uint32_t*)(smem + A2LO);
        const int r = r0;
#pragma unroll 1
        for (int kc = 0; kc < 8; kc++) {
            __syncthreads();   // prior reads of the buffer being overwritten are done
            if (kc < 7) {
                uint32_t d = (uint32_t)__cvta_generic_to_shared(
                    smem + (((kc + 1) & 1) ? B2BUF1 : B2BUF0));
                const char* sh = (const char*)g_W2hi + (kc + 1) * 16384;
                const char* sl = (const char*)g_W2lo + (kc + 1) * 16384;
#pragma unroll
                for (int i = 0; i < 2; i++) {
                    cp16(d + (tid + i * NTHR) * 16,         sh + (tid + i * NTHR) * 16);
                    cp16(d + 16384 + (tid + i * NTHR) * 16, sl + (tid + i * NTHR) * 16);
                }
                CP_COMMIT();
                CP_WAIT(1);    // chunk kc has landed
            } else {
                CP_WAIT(0);
            }
            __syncthreads();   // chunk kc visible to all warps
            const char* buf = smem + ((kc & 1) ? B2BUF1 : B2BUF0);
#pragma unroll
            for (int ks = 0; ks < 2; ks++) {
                int kp = kc * 16 + ks * 8 + (lane & 3);
                uint32_t ah[4], al[4];
                ah[0] = Ah[r * 132 + kp];      ah[1] = Ah[(r + 8) * 132 + kp];
                ah[2] = Ah[r * 132 + kp + 4];  ah[3] = Ah[(r + 8) * 132 + kp + 4];
                al[0] = Al[r * 132 + kp];      al[1] = Al[(r + 8) * 132 + kp];
                al[2] = Al[r * 132 + kp + 4];  al[3] = Al[(r + 8) * 132 + kp + 4];
#pragma unroll
                for (int tl = 0; tl < 16; tl++) {
                    int nt = nhalf * 16 + tl;
                    uint2 bh = *(const uint2*)(buf + (size_t)((nt * 2 + ks) * 32 + lane) * 8);
                    uint2 bl = *(const uint2*)(buf + 16384 + (size_t)((nt * 2 + ks) * 32 + lane) * 8);
                    mma_bf16(acc[tl], ah, (const uint32_t*)&bh);
                    mma_bf16(acc[tl], ah, (const uint32_t*)&bl);
                    mma_bf16(acc[tl], al, (const uint32_t*)&bh);
                }
            }
        }
    }

    // ---- epilogue 2: bias, LN2, ReLU, dot W3, sigmoid ----
    const float* b2s  = (const float*)(smem + OFF_B2S);
    const float* g2s  = (const float*)(smem + OFF_G2S);
    const float* be2s = (const float*)(smem + OFF_BE2S);
    const float* w3s  = (const float*)(smem + OFF_W3S);
    {
        float sa = 0.f, s2a = 0.f, sb = 0.f, s2b = 0.f;
#pragma unroll
        for (int tl = 0; tl < 16; tl++) {
            int c0 = nhalf * 128 + tl * 8 + (lane & 3) * 2;
            acc[tl][0] += b2s[c0]; acc[tl][1] += b2s[c0 + 1];
            acc[tl][2] += b2s[c0]; acc[tl][3] += b2s[c0 + 1];
            sa += acc[tl][0] + acc[tl][1]; s2a += acc[tl][0]*acc[tl][0] + acc[tl][1]*acc[tl][1];
            sb += acc[tl][2] + acc[tl][3]; s2b += acc[tl][2]*acc[tl][2] + acc[tl][3]*acc[tl][3];
        }
#pragma unroll
        for (int o = 1; o <= 2; o <<= 1) {
            sa += __shfl_xor_sync(0xffffffffu, sa, o);  s2a += __shfl_xor_sync(0xffffffffu, s2a, o);
            sb += __shfl_xor_sync(0xffffffffu, sb, o);  s2b += __shfl_xor_sync(0xffffffffu, s2b, o);
        }
        if ((lane & 3) == 0) {
            lnex[r0 * 2 + nhalf] = make_float2(sa, s2a);
            lnex[r1 * 2 + nhalf] = make_float2(sb, s2b);
        }
    }
    __syncthreads();
    {
        float2 a0 = lnex[r0 * 2 + 0], a1 = lnex[r0 * 2 + 1];
        float2 b0 = lnex[r1 * 2 + 0], b1v = lnex[r1 * 2 + 1];
        float mua = (a0.x + a1.x) * (1.f / HH);
        float rsa = rsqrtf((a0.y + a1.y) * (1.f / HH) - mua * mua + EPSLN);
        float mub = (b0.x + b1v.x) * (1.f / HH);
        float rsb = rsqrtf((b0.y + b1v.y) * (1.f / HH) - mub * mub + EPSLN);
        float pa = 0.f, pb = 0.f;
#pragma unroll
        for (int tl = 0; tl < 16; tl++) {
            int c0 = nhalf * 128 + tl * 8 + (lane & 3) * 2;
            float ga = g2s[c0], gb = g2s[c0 + 1], ba = be2s[c0], bb = be2s[c0 + 1];
            float w0 = w3s[c0], w1 = w3s[c0 + 1];
            pa = fmaf(fmaxf((acc[tl][0] - mua) * rsa * ga + ba, 0.f), w0, pa);
            pa = fmaf(fmaxf((acc[tl][1] - mua) * rsa * gb + bb, 0.f), w1, pa);
            pb = fmaf(fmaxf((acc[tl][2] - mub) * rsb * ga + ba, 0.f), w0, pb);
            pb = fmaf(fmaxf((acc[tl][3] - mub) * rsb * gb + bb, 0.f), w1, pb);
        }
#pragma unroll
        for (int o = 1; o <= 2; o <<= 1) {
            pa += __shfl_xor_sync(0xffffffffu, pa, o);
            pb += __shfl_xor_sync(0xffffffffu, pb, o);
        }
        float* pex = (float*)(smem + OFF_PEX);
        if ((lane & 3) == 0) {
            pex[r0 * 2 + nhalf] = pa;
            pex[r1 * 2 + nhalf] = pb;
        }
    }
    __syncthreads();
    if (tid < TE) {
        float* pex = (float*)(smem + OFF_PEX);
        float p = pex[tid * 2] + pex[tid * 2 + 1] + b3[0];
        int eg = e0 + tid;
        if (eg < E) out[eg] = 1.f / (1.f + expf(-p));
    }
}

extern "C" void kernel_launch(void* const* d_in, const int* in_sizes, int n_in,
                              void* d_out, int out_size)
{
    const float* h   = (const float*)d_in[0];
    const int*   src = (const int*)d_in[1];
    const int*   dst = (const int*)d_in[2];
    const float* W1 = (const float*)d_in[3];  const float* b1 = (const float*)d_in[4];
    const float* g1 = (const float*)d_in[5];  const float* be1 = (const float*)d_in[6];
    const float* W2 = (const float*)d_in[7];  const float* b2 = (const float*)d_in[8];
    const float* g2 = (const float*)d_in[9];  const float* be2 = (const float*)d_in[10];
    const float* W3 = (const float*)d_in[11]; const float* b3 = (const float*)d_in[12];

    int E  = in_sizes[1];
    int Nn = in_sizes[0] / DD;

    prep_kernel<<<(8192 + 16384 + 255) / 256, 256>>>(W1, W2);

    cudaFuncSetAttribute(mlp_mma_kernel,
                         cudaFuncAttributeMaxDynamicSharedMemorySize, SMEM_BYTES);
    int grid = (E + TE - 1) / TE;
    mlp_mma_kernel<<<grid, NTHR, SMEM_BYTES>>>(
        h, src, dst, b1, g1, be1, b2, g2, be2, W3, b3,
        (float*)d_out, E, Nn);
}

// round 6
// speedup vs baseline: 3.2004x; 1.0129x over previous
#include <cuda_runtime.h>
#include <cuda_bf16.h>
#include <math.h>
#include <stdint.h>

#define NTHR 512
#define TE   128
#define DD   128
#define HH   256
#define EPSLN 1e-5f

// ---------------- smem layout (byte offsets) ----------------
#define OFF_B1S   0
#define OFF_G1S   1024
#define OFF_BE1S  2048
#define OFF_B2S   3072
#define OFF_G2S   4096
#define OFF_BE2S  5120
#define OFF_W3S   6144
#define OFF_LNEX  7168      // 128 rows x 4 quarters x float2 = 4096
#define OFF_PEX   11264     // 128 rows x 4 quarters x float = 2048
#define TILES     13312
// phase 1: A1 (128x128 bf16, row stride 68 words) hi/lo ; B1 blobs hi/lo
#define A1HI  (TILES)                  // 34816
#define A1LO  (TILES + 34816)
#define B1HI  (TILES + 69632)          // 65536
#define B1LO  (TILES + 135168)         // ends TILES+200704
// phase 2 (alias): A2 (128x256 bf16, row stride 132 words) hi/lo ; B2 double buffer
#define A2HI   (TILES)                 // 67584
#define A2LO   (TILES + 67584)
#define B2BUF0 (TILES + 135168)        // 32768 each (hi 16384 | lo 16384)
#define B2BUF1 (TILES + 167936)
#define SMEM_BYTES (TILES + 200704)    // 214016

// fragment-ordered weight blobs:
// W1 blob slot = ((ntile*8 + kstep)*32 + lane) -> 8 bytes
//   {W[n][k0],W[n][k0+1], W[n][k0+8],W[n][k0+9]}, n = ntile*8 + lane/4, k0 = kstep*16 + (lane%4)*2
__device__ __align__(16) unsigned char g_W1hi[65536];
__device__ __align__(16) unsigned char g_W1lo[65536];
// W2 blob: [kchunk 8][ntile 32][kstep 2][lane 32] x 8B   (chunk = K 32)
__device__ __align__(16) unsigned char g_W2hi[131072];
__device__ __align__(16) unsigned char g_W2lo[131072];

__device__ __forceinline__ void split_bf16(float x, uint16_t& hi, uint16_t& lo) {
    __nv_bfloat16 h = __float2bfloat16_rn(x);
    __nv_bfloat16 l = __float2bfloat16_rn(x - __bfloat162float(h));
    hi = __bfloat16_as_ushort(h);
    lo = __bfloat16_as_ushort(l);
}

__device__ __forceinline__ void mma_bf16(float d[4], const uint32_t a[4], const uint32_t b[2]) {
    asm volatile(
        "mma.sync.aligned.m16n8k16.row.col.f32.bf16.bf16.f32 "
        "{%0,%1,%2,%3}, {%4,%5,%6,%7}, {%8,%9}, {%0,%1,%2,%3};"
        : "+f"(d[0]), "+f"(d[1]), "+f"(d[2]), "+f"(d[3])
        : "r"(a[0]), "r"(a[1]), "r"(a[2]), "r"(a[3]), "r"(b[0]), "r"(b[1]));
}

__device__ __forceinline__ void cp16(uint32_t dst_smem, const void* gsrc) {
    asm volatile("cp.async.cg.shared.global [%0], [%1], 16;" :: "r"(dst_smem), "l"(gsrc));
}
#define CP_COMMIT() asm volatile("cp.async.commit_group;" ::: "memory")
#define CP_WAIT(N)  asm volatile("cp.async.wait_group %0;" :: "n"(N) : "memory")

// ---------------- prep: split + repack weights into fragment-ordered blobs ----------------
__global__ void prep_kernel(const float* __restrict__ W1, const float* __restrict__ W2) {
    int i = blockIdx.x * blockDim.x + threadIdx.x;
    if (i < 8192) {                                    // W1 [256n][128k], 32 nt x 8 ks
        int nt = i >> 8, ks = (i >> 5) & 7, lane = i & 31;
        int n = nt * 8 + (lane >> 2);
        int k0 = ks * 16 + (lane & 3) * 2;
        const float* w = W1 + n * 128 + k0;
        uint16_t h0,h1,h2,h3,l0,l1,l2,l3;
        split_bf16(w[0], h0, l0); split_bf16(w[1], h1, l1);
        split_bf16(w[8], h2, l2); split_bf16(w[9], h3, l3);
        ((uint2*)g_W1hi)[i] = make_uint2((uint32_t)h0 | ((uint32_t)h1 << 16),
                                         (uint32_t)h2 | ((uint32_t)h3 << 16));
        ((uint2*)g_W1lo)[i] = make_uint2((uint32_t)l0 | ((uint32_t)l1 << 16),
                                         (uint32_t)l2 | ((uint32_t)l3 << 16));
    } else if (i < 8192 + 16384) {                     // W2 [256n][256k], 8 kc x 32 nt x 2 ks
        int j = i - 8192;
        int kc = j >> 11, nt = (j >> 6) & 31, ks = (j >> 5) & 1, lane = j & 31;
        int n = nt * 8 + (lane >> 2);
        int k0 = kc * 32 + ks * 16 + (lane & 3) * 2;
        const float* w = W2 + n * 256 + k0;
        uint16_t h0,h1,h2,h3,l0,l1,l2,l3;
        split_bf16(w[0], h0, l0); split_bf16(w[1], h1, l1);
        split_bf16(w[8], h2, l2); split_bf16(w[9], h3, l3);
        ((uint2*)g_W2hi)[j] = make_uint2((uint32_t)h0 | ((uint32_t)h1 << 16),
                                         (uint32_t)h2 | ((uint32_t)h3 << 16));
        ((uint2*)g_W2lo)[j] = make_uint2((uint32_t)l0 | ((uint32_t)l1 << 16),
                                         (uint32_t)l2 | ((uint32_t)l3 << 16));
    }
}

// ---------------- main ----------------
__global__ void __launch_bounds__(NTHR, 1)
mlp_mma_kernel(const float* __restrict__ h,
               const int* __restrict__ src, const int* __restrict__ dst,
               const float* __restrict__ b1, const float* __restrict__ g1, const float* __restrict__ be1,
               const float* __restrict__ b2, const float* __restrict__ g2, const float* __restrict__ be2,
               const float* __restrict__ W3, const float* __restrict__ b3,
               float* __restrict__ out, int E, int Nn)
{
    extern __shared__ __align__(16) char smem[];
    const int tid   = threadIdx.x;
    const int wid   = tid >> 5;
    const int lane  = tid & 31;
    const int rowt  = wid & 3;          // row group: rows [rowt*32, rowt*32+32)
    const int nq    = wid >> 2;         // col quarter: cols [nq*64, nq*64+64)
    const int e0    = blockIdx.x * TE;

    // --- async-stage B1 blobs (131072 B) ---
    {
        uint32_t dh = (uint32_t)__cvta_generic_to_shared(smem + B1HI);
        uint32_t dl = (uint32_t)__cvta_generic_to_shared(smem + B1LO);
#pragma unroll
        for (int i = 0; i < 8; i++) {
            cp16(dh + (tid + i * NTHR) * 16, (const char*)g_W1hi + (tid + i * NTHR) * 16);
            cp16(dl + (tid + i * NTHR) * 16, (const char*)g_W1lo + (tid + i * NTHR) * 16);
        }
        CP_COMMIT();
    }

    // --- params ---
    if (tid < HH) {
        ((float*)(smem + OFF_B1S))[tid]  = b1[tid];
        ((float*)(smem + OFF_G1S))[tid]  = g1[tid];
        ((float*)(smem + OFF_BE1S))[tid] = be1[tid];
        ((float*)(smem + OFF_B2S))[tid]  = b2[tid];
        ((float*)(smem + OFF_G2S))[tid]  = g2[tid];
        ((float*)(smem + OFF_BE2S))[tid] = be2[tid];
        ((float*)(smem + OFF_W3S))[tid]  = W3[tid];
    }

    // --- gather x = h[src]*h[dst], split to bf16 hi/lo, A1 row-major (stride 68 words) ---
    {
        int row = tid >> 2, q = tid & 3;
        int eg = e0 + row;
        int si = 0, di = 0;
        if (eg < E) { si = src[eg]; di = dst[eg]; }
        if ((unsigned)si >= (unsigned)Nn) si = 0;
        if ((unsigned)di >= (unsigned)Nn) di = 0;
        const float4* ps = (const float4*)(h + (size_t)si * DD) + q * 8;
        const float4* pd = (const float4*)(h + (size_t)di * DD) + q * 8;
        uint32_t* oh = (uint32_t*)(smem + A1HI) + row * 68 + q * 16;
        uint32_t* ol = (uint32_t*)(smem + A1LO) + row * 68 + q * 16;
#pragma unroll
        for (int i = 0; i < 8; i++) {
            float4 a = ps[i], b = pd[i];
            uint16_t h0,h1,h2,h3,l0,l1,l2,l3;
            split_bf16(a.x * b.x, h0, l0); split_bf16(a.y * b.y, h1, l1);
            split_bf16(a.z * b.z, h2, l2); split_bf16(a.w * b.w, h3, l3);
            oh[i * 2]     = (uint32_t)h0 | ((uint32_t)h1 << 16);
            oh[i * 2 + 1] = (uint32_t)h2 | ((uint32_t)h3 << 16);
            ol[i * 2]     = (uint32_t)l0 | ((uint32_t)l1 << 16);
            ol[i * 2 + 1] = (uint32_t)l2 | ((uint32_t)l3 << 16);
        }
    }
    CP_WAIT(0);
    __syncthreads();

    // acc0 = rows [rowt*32 .. +16), acc1 = rows [rowt*32+16 .. +32), cols nq*64 + tl*8
    float acc0[8][4], acc1[8][4];
#pragma unroll
    for (int t = 0; t < 8; t++) {
        acc0[t][0]=acc0[t][1]=acc0[t][2]=acc0[t][3]=0.f;
        acc1[t][0]=acc1[t][1]=acc1[t][2]=acc1[t][3]=0.f;
    }

    const int rbase = rowt * 32 + (lane >> 2);

    // ---- layer 1: K=128, 8 ksteps, 3-term split, 2 row-subtiles per B fragment ----
    {
        const uint32_t* Ah = (const uint32_t*)(smem + A1HI);
        const uint32_t* Al = (const uint32_t*)(smem + A1LO);
#pragma unroll 1
        for (int ks = 0; ks < 8; ks++) {
            int kp = ks * 8 + (lane & 3);
            uint32_t ah0[4], al0[4], ah1[4], al1[4];
            ah0[0] = Ah[rbase * 68 + kp];            ah0[1] = Ah[(rbase + 8) * 68 + kp];
            ah0[2] = Ah[rbase * 68 + kp + 4];        ah0[3] = Ah[(rbase + 8) * 68 + kp + 4];
            ah1[0] = Ah[(rbase + 16) * 68 + kp];     ah1[1] = Ah[(rbase + 24) * 68 + kp];
            ah1[2] = Ah[(rbase + 16) * 68 + kp + 4]; ah1[3] = Ah[(rbase + 24) * 68 + kp + 4];
            al0[0] = Al[rbase * 68 + kp];            al0[1] = Al[(rbase + 8) * 68 + kp];
            al0[2] = Al[rbase * 68 + kp + 4];        al0[3] = Al[(rbase + 8) * 68 + kp + 4];
            al1[0] = Al[(rbase + 16) * 68 + kp];     al1[1] = Al[(rbase + 24) * 68 + kp];
            al1[2] = Al[(rbase + 16) * 68 + kp + 4]; al1[3] = Al[(rbase + 24) * 68 + kp + 4];
#pragma unroll
            for (int tl = 0; tl < 8; tl++) {
                int nt = nq * 8 + tl;
                uint2 bh = *(const uint2*)(smem + B1HI + (size_t)((nt * 8 + ks) * 32 + lane) * 8);
                uint2 bl = *(const uint2*)(smem + B1LO + (size_t)((nt * 8 + ks) * 32 + lane) * 8);
                mma_bf16(acc0[tl], ah0, (const uint32_t*)&bh);
                mma_bf16(acc0[tl], ah0, (const uint32_t*)&bl);
                mma_bf16(acc0[tl], al0, (const uint32_t*)&bh);
                mma_bf16(acc1[tl], ah1, (const uint32_t*)&bh);
                mma_bf16(acc1[tl], ah1, (const uint32_t*)&bl);
                mma_bf16(acc1[tl], al1, (const uint32_t*)&bh);
            }
        }
    }

    // rows owned by this thread
    const int r0 = rbase, r1 = rbase + 8, r2 = rbase + 16, r3 = rbase + 24;
    const float* b1s  = (const float*)(smem + OFF_B1S);
    const float* g1s  = (const float*)(smem + OFF_G1S);
    const float* be1s = (const float*)(smem + OFF_BE1S);
    float2* lnex = (float2*)(smem + OFF_LNEX);

    // ---- epilogue 1: bias + partial LN stats (per col-quarter) ----
    {
        float sa=0.f,s2a=0.f, sb=0.f,s2b=0.f, sc=0.f,s2c=0.f, sd=0.f,s2d=0.f;
#pragma unroll
        for (int tl = 0; tl < 8; tl++) {
            int c0 = nq * 64 + tl * 8 + (lane & 3) * 2;
            float bb0 = b1s[c0], bb1 = b1s[c0 + 1];
            acc0[tl][0] += bb0; acc0[tl][1] += bb1; acc0[tl][2] += bb0; acc0[tl][3] += bb1;
            acc1[tl][0] += bb0; acc1[tl][1] += bb1; acc1[tl][2] += bb0; acc1[tl][3] += bb1;
            sa += acc0[tl][0] + acc0[tl][1]; s2a += acc0[tl][0]*acc0[tl][0] + acc0[tl][1]*acc0[tl][1];
            sb += acc0[tl][2] + acc0[tl][3]; s2b += acc0[tl][2]*acc0[tl][2] + acc0[tl][3]*acc0[tl][3];
            sc += acc1[tl][0] + acc1[tl][1]; s2c += acc1[tl][0]*acc1[tl][0] + acc1[tl][1]*acc1[tl][1];
            sd += acc1[tl][2] + acc1[tl][3]; s2d += acc1[tl][2]*acc1[tl][2] + acc1[tl][3]*acc1[tl][3];
        }
#pragma unroll
        for (int o = 1; o <= 2; o <<= 1) {
            sa += __shfl_xor_sync(0xffffffffu, sa, o);  s2a += __shfl_xor_sync(0xffffffffu, s2a, o);
            sb += __shfl_xor_sync(0xffffffffu, sb, o);  s2b += __shfl_xor_sync(0xffffffffu, s2b, o);
            sc += __shfl_xor_sync(0xffffffffu, sc, o);  s2c += __shfl_xor_sync(0xffffffffu, s2c, o);
            sd += __shfl_xor_sync(0xffffffffu, sd, o);  s2d += __shfl_xor_sync(0xffffffffu, s2d, o);
        }
        if ((lane & 3) == 0) {
            lnex[r0 * 4 + nq] = make_float2(sa, s2a);
            lnex[r1 * 4 + nq] = make_float2(sb, s2b);
            lnex[r2 * 4 + nq] = make_float2(sc, s2c);
            lnex[r3 * 4 + nq] = make_float2(sd, s2d);
        }
    }
    __syncthreads();   // layer-1 mma + stats done everywhere; A1/B1 now dead

    // prefetch W2 chunk 0 into buf0
    {
        uint32_t d0 = (uint32_t)__cvta_generic_to_shared(smem + B2BUF0);
#pragma unroll
        for (int i = 0; i < 2; i++) {
            cp16(d0 + (tid + i * NTHR) * 16,           (const char*)g_W2hi + (tid + i * NTHR) * 16);
            cp16(d0 + 16384 + (tid + i * NTHR) * 16,   (const char*)g_W2lo + (tid + i * NTHR) * 16);
        }
        CP_COMMIT();
    }

    // ---- LN1 transform + ReLU + split -> A2 (stride 132 words) ----
    {
        float mu[4], rs[4];
        int rr[4] = {r0, r1, r2, r3};
#pragma unroll
        for (int k = 0; k < 4; k++) {
            float2 q0 = lnex[rr[k] * 4 + 0], q1 = lnex[rr[k] * 4 + 1];
            float2 q2 = lnex[rr[k] * 4 + 2], q3 = lnex[rr[k] * 4 + 3];
            float s  = q0.x + q1.x + q2.x + q3.x;
            float s2 = q0.y + q1.y + q2.y + q3.y;
            mu[k] = s * (1.f / HH);
            rs[k] = rsqrtf(s2 * (1.f / HH) - mu[k] * mu[k] + EPSLN);
        }
        uint32_t* A2h = (uint32_t*)(smem + A2HI);
        uint32_t* A2l = (uint32_t*)(smem + A2LO);
#pragma unroll
        for (int tl = 0; tl < 8; tl++) {
            int c0 = nq * 64 + tl * 8 + (lane & 3) * 2;
            float ga = g1s[c0], gb = g1s[c0 + 1], ba = be1s[c0], bb = be1s[c0 + 1];
            int w = c0 >> 1;
            float y0, y1; uint16_t hh0,hh1,ll0,ll1;
            y0 = fmaxf((acc0[tl][0] - mu[0]) * rs[0] * ga + ba, 0.f);
            y1 = fmaxf((acc0[tl][1] - mu[0]) * rs[0] * gb + bb, 0.f);
            split_bf16(y0, hh0, ll0); split_bf16(y1, hh1, ll1);
            A2h[r0 * 132 + w] = (uint32_t)hh0 | ((uint32_t)hh1 << 16);
            A2l[r0 * 132 + w] = (uint32_t)ll0 | ((uint32_t)ll1 << 16);
            y0 = fmaxf((acc0[tl][2] - mu[1]) * rs[1] * ga + ba, 0.f);
            y1 = fmaxf((acc0[tl][3] - mu[1]) * rs[1] * gb + bb, 0.f);
            split_bf16(y0, hh0, ll0); split_bf16(y1, hh1, ll1);
            A2h[r1 * 132 + w] = (uint32_t)hh0 | ((uint32_t)hh1 << 16);
            A2l[r1 * 132 + w] = (uint32_t)ll0 | ((uint32_t)ll1 << 16);
            y0 = fmaxf((acc1[tl][0] - mu[2]) * rs[2] * ga + ba, 0.f);
            y1 = fmaxf((acc1[tl][1] - mu[2]) * rs[2] * gb + bb, 0.f);
            split_bf16(y0, hh0, ll0); split_bf16(y1, hh1, ll1);
            A2h[r2 * 132 + w] = (uint32_t)hh0 | ((uint32_t)hh1 << 16);
            A2l[r2 * 132 + w] = (uint32_t)ll0 | ((uint32_t)ll1 << 16);
            y0 = fmaxf((acc1[tl][2] - mu[3]) * rs[3] * ga + ba, 0.f);
            y1 = fmaxf((acc1[tl][3] - mu[3]) * rs[3] * gb + bb, 0.f);
            split_bf16(y0, hh0, ll0); split_bf16(y1, hh1, ll1);
            A2h[r3 * 132 + w] = (uint32_t)hh0 | ((uint32_t)hh1 << 16);
            A2l[r3 * 132 + w] = (uint32_t)ll0 | ((uint32_t)ll1 << 16);
        }
    }

#pragma unroll
    for (int t = 0; t < 8; t++) {
        acc0[t][0]=acc0[t][1]=acc0[t][2]=acc0[t][3]=0.f;
        acc1[t][0]=acc1[t][1]=acc1[t][2]=acc1[t][3]=0.f;
    }

    // ---- layer 2: K=256 in 8 chunks of 32, double-buffered cp.async ----
    {
        const uint32_t* Ah = (const uint32_t*)(smem + A2HI);
        const uint32_t* Al = (const uint32_t*)(smem + A2LO);
#pragma unroll 1
        for (int kc = 0; kc < 8; kc++) {
            __syncthreads();   // prior reads of the buffer being overwritten are done
            if (kc < 7) {
                uint32_t d = (uint32_t)__cvta_generic_to_shared(
                    smem + (((kc + 1) & 1) ? B2BUF1 : B2BUF0));
                const char* sh = (const char*)g_W2hi + (kc + 1) * 16384;
                const char* sl = (const char*)g_W2lo + (kc + 1) * 16384;
#pragma unroll
                for (int i = 0; i < 2; i++) {
                    cp16(d + (tid + i * NTHR) * 16,         sh + (tid + i * NTHR) * 16);
                    cp16(d + 16384 + (tid + i * NTHR) * 16, sl + (tid + i * NTHR) * 16);
                }
                CP_COMMIT();
                CP_WAIT(1);    // chunk kc has landed
            } else {
                CP_WAIT(0);
            }
            __syncthreads();   // chunk kc visible to all warps
            const char* buf = smem + ((kc & 1) ? B2BUF1 : B2BUF0);
#pragma unroll
            for (int ks = 0; ks < 2; ks++) {
                int kp = kc * 16 + ks * 8 + (lane & 3);
                uint32_t ah0[4], al0[4], ah1[4], al1[4];
                ah0[0] = Ah[rbase * 132 + kp];            ah0[1] = Ah[(rbase + 8) * 132 + kp];
                ah0[2] = Ah[rbase * 132 + kp + 4];        ah0[3] = Ah[(rbase + 8) * 132 + kp + 4];
                ah1[0] = Ah[(rbase + 16) * 132 + kp];     ah1[1] = Ah[(rbase + 24) * 132 + kp];
                ah1[2] = Ah[(rbase + 16) * 132 + kp + 4]; ah1[3] = Ah[(rbase + 24) * 132 + kp + 4];
                al0[0] = Al[rbase * 132 + kp];            al0[1] = Al[(rbase + 8) * 132 + kp];
                al0[2] = Al[rbase * 132 + kp + 4];        al0[3] = Al[(rbase + 8) * 132 + kp + 4];
                al1[0] = Al[(rbase + 16) * 132 + kp];     al1[1] = Al[(rbase + 24) * 132 + kp];
                al1[2] = Al[(rbase + 16) * 132 + kp + 4]; al1[3] = Al[(rbase + 24) * 132 + kp + 4];
#pragma unroll
                for (int tl = 0; tl < 8; tl++) {
                    int nt = nq * 8 + tl;
                    uint2 bh = *(const uint2*)(buf + (size_t)((nt * 2 + ks) * 32 + lane) * 8);
                    uint2 bl = *(const uint2*)(buf + 16384 + (size_t)((nt * 2 + ks) * 32 + lane) * 8);
                    mma_bf16(acc0[tl], ah0, (const uint32_t*)&bh);
                    mma_bf16(acc0[tl], ah0, (const uint32_t*)&bl);
                    mma_bf16(acc0[tl], al0, (const uint32_t*)&bh);
                    mma_bf16(acc1[tl], ah1, (const uint32_t*)&bh);
                    mma_bf16(acc1[tl], ah1, (const uint32_t*)&bl);
                    mma_bf16(acc1[tl], al1, (const uint32_t*)&bh);
                }
            }
        }
    }

    // ---- epilogue 2: bias + partial LN stats ----
    const float* b2s  = (const float*)(smem + OFF_B2S);
    const float* g2s  = (const float*)(smem + OFF_G2S);
    const float* be2s = (const float*)(smem + OFF_BE2S);
    const float* w3s  = (const float*)(smem + OFF_W3S);
    {
        float sa=0.f,s2a=0.f, sb=0.f,s2b=0.f, sc=0.f,s2c=0.f, sd=0.f,s2d=0.f;
#pragma unroll
        for (int tl = 0; tl < 8; tl++) {
            int c0 = nq * 64 + tl * 8 + (lane & 3) * 2;
            float bb0 = b2s[c0], bb1 = b2s[c0 + 1];
            acc0[tl][0] += bb0; acc0[tl][1] += bb1; acc0[tl][2] += bb0; acc0[tl][3] += bb1;
            acc1[tl][0] += bb0; acc1[tl][1] += bb1; acc1[tl][2] += bb0; acc1[tl][3] += bb1;
            sa += acc0[tl][0] + acc0[tl][1]; s2a += acc0[tl][0]*acc0[tl][0] + acc0[tl][1]*acc0[tl][1];
            sb += acc0[tl][2] + acc0[tl][3]; s2b += acc0[tl][2]*acc0[tl][2] + acc0[tl][3]*acc0[tl][3];
            sc += acc1[tl][0] + acc1[tl][1]; s2c += acc1[tl][0]*acc1[tl][0] + acc1[tl][1]*acc1[tl][1];
            sd += acc1[tl][2] + acc1[tl][3]; s2d += acc1[tl][2]*acc1[tl][2] + acc1[tl][3]*acc1[tl][3];
        }
#pragma unroll
        for (int o = 1; o <= 2; o <<= 1) {
            sa += __shfl_xor_sync(0xffffffffu, sa, o);  s2a += __shfl_xor_sync(0xffffffffu, s2a, o);
            sb += __shfl_xor_sync(0xffffffffu, sb, o);  s2b += __shfl_xor_sync(0xffffffffu, s2b, o);
            sc += __shfl_xor_sync(0xffffffffu, sc, o);  s2c += __shfl_xor_sync(0xffffffffu, s2c, o);
            sd += __shfl_xor_sync(0xffffffffu, sd, o);  s2d += __shfl_xor_sync(0xffffffffu, s2d, o);
        }
        if ((lane & 3) == 0) {
            lnex[r0 * 4 + nq] = make_float2(sa, s2a);
            lnex[r1 * 4 + nq] = make_float2(sb, s2b);
            lnex[r2 * 4 + nq] = make_float2(sc, s2c);
            lnex[r3 * 4 + nq] = make_float2(sd, s2d);
        }
    }
    __syncthreads();
    // ---- LN2 + ReLU + dot W3 partials ----
    {
        float mu[4], rs[4];
        int rr[4] = {r0, r1, r2, r3};
#pragma unroll
        for (int k = 0; k < 4; k++) {
            float2 q0 = lnex[rr[k] * 4 + 0], q1 = lnex[rr[k] * 4 + 1];
            float2 q2 = lnex[rr[k] * 4 + 2], q3 = lnex[rr[k] * 4 + 3];
            float s  = q0.x + q1.x + q2.x + q3.x;
            float s2 = q0.y + q1.y + q2.y + q3.y;
            mu[k] = s * (1.f / HH);
            rs[k] = rsqrtf(s2 * (1.f / HH) - mu[k] * mu[k] + EPSLN);
        }
        float pa = 0.f, pb = 0.f, pc = 0.f, pd = 0.f;
#pragma unroll
        for (int tl = 0; tl < 8; tl++) {
            int c0 = nq * 64 + tl * 8 + (lane & 3) * 2;
            float ga = g2s[c0], gb = g2s[c0 + 1], ba = be2s[c0], bb = be2s[c0 + 1];
            float w0 = w3s[c0], w1 = w3s[c0 + 1];
            pa = fmaf(fmaxf((acc0[tl][0] - mu[0]) * rs[0] * ga + ba, 0.f), w0, pa);
            pa = fmaf(fmaxf((acc0[tl][1] - mu[0]) * rs[0] * gb + bb, 0.f), w1, pa);
            pb = fmaf(fmaxf((acc0[tl][2] - mu[1]) * rs[1] * ga + ba, 0.f), w0, pb);
            pb = fmaf(fmaxf((acc0[tl][3] - mu[1]) * rs[1] * gb + bb, 0.f), w1, pb);
            pc = fmaf(fmaxf((acc1[tl][0] - mu[2]) * rs[2] * ga + ba, 0.f), w0, pc);
            pc = fmaf(fmaxf((acc1[tl][1] - mu[2]) * rs[2] * gb + bb, 0.f), w1, pc);
            pd = fmaf(fmaxf((acc1[tl][2] - mu[3]) * rs[3] * ga + ba, 0.f), w0, pd);
            pd = fmaf(fmaxf((acc1[tl][3] - mu[3]) * rs[3] * gb + bb, 0.f), w1, pd);
        }
#pragma unroll
        for (int o = 1; o <= 2; o <<= 1) {
            pa += __shfl_xor_sync(0xffffffffu, pa, o);
            pb += __shfl_xor_sync(0xffffffffu, pb, o);
            pc += __shfl_xor_sync(0xffffffffu, pc, o);
            pd += __shfl_xor_sync(0xffffffffu, pd, o);
        }
        float* pex = (float*)(smem + OFF_PEX);
        if ((lane & 3) == 0) {
            pex[r0 * 4 + nq] = pa;
            pex[r1 * 4 + nq] = pb;
            pex[r2 * 4 + nq] = pc;
            pex[r3 * 4 + nq] = pd;
        }
    }
    __syncthreads();
    if (tid < TE) {
        float* pex = (float*)(smem + OFF_PEX);
        float p = pex[tid * 4] + pex[tid * 4 + 1] + pex[tid * 4 + 2] + pex[tid * 4 + 3] + b3[0];
        int eg = e0 + tid;
        if (eg < E) out[eg] = 1.f / (1.f + expf(-p));
    }
}

extern "C" void kernel_launch(void* const* d_in, const int* in_sizes, int n_in,
                              void* d_out, int out_size)
{
    const float* h   = (const float*)d_in[0];
    const int*   src = (const int*)d_in[1];
    const int*   dst = (const int*)d_in[2];
    const float* W1 = (const float*)d_in[3];  const float* b1 = (const float*)d_in[4];
    const float* g1 = (const float*)d_in[5];  const float* be1 = (const float*)d_in[6];
    const float* W2 = (const float*)d_in[7];  const float* b2 = (const float*)d_in[8];
    const float* g2 = (const float*)d_in[9];  const float* be2 = (const float*)d_in[10];
    const float* W3 = (const float*)d_in[11]; const float* b3 = (const float*)d_in[12];

    int E  = in_sizes[1];
    int Nn = in_sizes[0] / DD;

    prep_kernel<<<(8192 + 16384 + 255) / 256, 256>>>(W1, W2);

    cudaFuncSetAttribute(mlp_mma_kernel,
                         cudaFuncAttributeMaxDynamicSharedMemorySize, SMEM_BYTES);
    int grid = (E + TE - 1) / TE;
    mlp_mma_kernel<<<grid, NTHR, SMEM_BYTES>>>(
        h, src, dst, b1, g1, be1, b2, g2, be2, W3, b3,
        (float*)d_out, E, Nn);
}

// round 7
// speedup vs baseline: 4.4916x; 1.4034x over previous
#include <cuda_runtime.h>
#include <cuda_fp16.h>
#include <math.h>
#include <stdint.h>

#define NTHR 512
#define TE   128
#define DD   128
#define HH   256
#define EPSLN 1e-5f

// ---------------- smem layout (byte offsets) ----------------
#define OFF_B1S   0
#define OFF_G1S   1024
#define OFF_BE1S  2048
#define OFF_B2S   3072
#define OFF_G2S   4096
#define OFF_BE2S  5120
#define OFF_W3S   6144
#define OFF_LNEX  7168      // 128 rows x 4 quarters x float2 = 4096
#define OFF_PEX   11264     // 128 rows x 4 quarters x float = 2048
#define TILES     13312
// phase 1: A1 (128x128 fp16, row stride 68 words) ; B1 blobs hi/lo
#define A1S   (TILES)                  // 34816
#define B1HI  (TILES + 34816)          // 65536
#define B1LO  (TILES + 100352)         // ends TILES+165888
// phase 2 (alias): A2 (128x256 fp16, row stride 132 words) ; B2 double buffer
#define A2S    (TILES)                 // 67584
#define B2BUF0 (TILES + 67584)         // 32768 (hi 16384 | lo 16384)
#define B2BUF1 (TILES + 100352)        // ends TILES+133120
#define SMEM_BYTES (TILES + 165888)    // 179200

// fragment-ordered weight blobs (fp16):
// W1 blob slot = ((ntile*8 + kstep)*32 + lane) -> 8 bytes
//   {W[n][k0],W[n][k0+1], W[n][k0+8],W[n][k0+9]}, n = ntile*8 + lane/4, k0 = kstep*16 + (lane%4)*2
__device__ __align__(16) unsigned char g_W1hi[65536];
__device__ __align__(16) unsigned char g_W1lo[65536];
// W2 blob: [kchunk 8][ntile 32][kstep 2][lane 32] x 8B   (chunk = K 32)
__device__ __align__(16) unsigned char g_W2hi[131072];
__device__ __align__(16) unsigned char g_W2lo[131072];

__device__ __forceinline__ void split_f16(float x, uint16_t& hi, uint16_t& lo) {
    __half h = __float2half_rn(x);
    __half l = __float2half_rn(x - __half2float(h));
    hi = __half_as_ushort(h);
    lo = __half_as_ushort(l);
}

__device__ __forceinline__ uint32_t pack_f16x2(float a, float b) {
    __half2 h = __floats2half2_rn(a, b);
    return *reinterpret_cast<uint32_t*>(&h);
}

__device__ __forceinline__ void mma_f16(float d[4], const uint32_t a[4], const uint32_t b[2]) {
    asm volatile(
        "mma.sync.aligned.m16n8k16.row.col.f32.f16.f16.f32 "
        "{%0,%1,%2,%3}, {%4,%5,%6,%7}, {%8,%9}, {%0,%1,%2,%3};"
        : "+f"(d[0]), "+f"(d[1]), "+f"(d[2]), "+f"(d[3])
        : "r"(a[0]), "r"(a[1]), "r"(a[2]), "r"(a[3]), "r"(b[0]), "r"(b[1]));
}

__device__ __forceinline__ void cp16(uint32_t dst_smem, const void* gsrc) {
    asm volatile("cp.async.cg.shared.global [%0], [%1], 16;" :: "r"(dst_smem), "l"(gsrc));
}
#define CP_COMMIT() asm volatile("cp.async.commit_group;" ::: "memory")
#define CP_WAIT(N)  asm volatile("cp.async.wait_group %0;" :: "n"(N) : "memory")

// ---------------- prep: split + repack weights into fragment-ordered fp16 blobs ----------------
__global__ void prep_kernel(const float* __restrict__ W1, const float* __restrict__ W2) {
    int i = blockIdx.x * blockDim.x + threadIdx.x;
    if (i < 8192) {                                    // W1 [256n][128k], 32 nt x 8 ks
        int nt = i >> 8, ks = (i >> 5) & 7, lane = i & 31;
        int n = nt * 8 + (lane >> 2);
        int k0 = ks * 16 + (lane & 3) * 2;
        const float* w = W1 + n * 128 + k0;
        uint16_t h0,h1,h2,h3,l0,l1,l2,l3;
        split_f16(w[0], h0, l0); split_f16(w[1], h1, l1);
        split_f16(w[8], h2, l2); split_f16(w[9], h3, l3);
        ((uint2*)g_W1hi)[i] = make_uint2((uint32_t)h0 | ((uint32_t)h1 << 16),
                                         (uint32_t)h2 | ((uint32_t)h3 << 16));
        ((uint2*)g_W1lo)[i] = make_uint2((uint32_t)l0 | ((uint32_t)l1 << 16),
                                         (uint32_t)l2 | ((uint32_t)l3 << 16));
    } else if (i < 8192 + 16384) {                     // W2 [256n][256k], 8 kc x 32 nt x 2 ks
        int j = i - 8192;
        int kc = j >> 11, nt = (j >> 6) & 31, ks = (j >> 5) & 1, lane = j & 31;
        int n = nt * 8 + (lane >> 2);
        int k0 = kc * 32 + ks * 16 + (lane & 3) * 2;
        const float* w = W2 + n * 256 + k0;
        uint16_t h0,h1,h2,h3,l0,l1,l2,l3;
        split_f16(w[0], h0, l0); split_f16(w[1], h1, l1);
        split_f16(w[8], h2, l2); split_f16(w[9], h3, l3);
        ((uint2*)g_W2hi)[j] = make_uint2((uint32_t)h0 | ((uint32_t)h1 << 16),
                                         (uint32_t)h2 | ((uint32_t)h3 << 16));
        ((uint2*)g_W2lo)[j] = make_uint2((uint32_t)l0 | ((uint32_t)l1 << 16),
                                         (uint32_t)l2 | ((uint32_t)l3 << 16));
    }
}

// ---------------- main ----------------
__global__ void __launch_bounds__(NTHR, 1)
mlp_mma_kernel(const float* __restrict__ h,
               const int* __restrict__ src, const int* __restrict__ dst,
               const float* __restrict__ b1, const float* __restrict__ g1, const float* __restrict__ be1,
               const float* __restrict__ b2, const float* __restrict__ g2, const float* __restrict__ be2,
               const float* __restrict__ W3, const float* __restrict__ b3,
               float* __restrict__ out, int E, int Nn)
{
    extern __shared__ __align__(16) char smem[];
    const int tid   = threadIdx.x;
    const int wid   = tid >> 5;
    const int lane  = tid & 31;
    const int rowt  = wid & 3;          // row group: rows [rowt*32, rowt*32+32)
    const int nq    = wid >> 2;         // col quarter: cols [nq*64, nq*64+64)
    const int e0    = blockIdx.x * TE;

    // --- async-stage B1 blobs (131072 B) ---
    {
        uint32_t dh = (uint32_t)__cvta_generic_to_shared(smem + B1HI);
        uint32_t dl = (uint32_t)__cvta_generic_to_shared(smem + B1LO);
#pragma unroll
        for (int i = 0; i < 8; i++) {
            cp16(dh + (tid + i * NTHR) * 16, (const char*)g_W1hi + (tid + i * NTHR) * 16);
            cp16(dl + (tid + i * NTHR) * 16, (const char*)g_W1lo + (tid + i * NTHR) * 16);
        }
        CP_COMMIT();
    }

    // --- params ---
    if (tid < HH) {
        ((float*)(smem + OFF_B1S))[tid]  = b1[tid];
        ((float*)(smem + OFF_G1S))[tid]  = g1[tid];
        ((float*)(smem + OFF_BE1S))[tid] = be1[tid];
        ((float*)(smem + OFF_B2S))[tid]  = b2[tid];
        ((float*)(smem + OFF_G2S))[tid]  = g2[tid];
        ((float*)(smem + OFF_BE2S))[tid] = be2[tid];
        ((float*)(smem + OFF_W3S))[tid]  = W3[tid];
    }

    // --- gather x = h[src]*h[dst] -> fp16, A1 row-major (stride 68 words) ---
    {
        int row = tid >> 2, q = tid & 3;
        int eg = e0 + row;
        int si = 0, di = 0;
        if (eg < E) { si = src[eg]; di = dst[eg]; }
        if ((unsigned)si >= (unsigned)Nn) si = 0;
        if ((unsigned)di >= (unsigned)Nn) di = 0;
        const float4* ps = (const float4*)(h + (size_t)si * DD) + q * 8;
        const float4* pd = (const float4*)(h + (size_t)di * DD) + q * 8;
        uint32_t* oh = (uint32_t*)(smem + A1S) + row * 68 + q * 16;
#pragma unroll
        for (int i = 0; i < 8; i++) {
            float4 a = ps[i], b = pd[i];
            oh[i * 2]     = pack_f16x2(a.x * b.x, a.y * b.y);
            oh[i * 2 + 1] = pack_f16x2(a.z * b.z, a.w * b.w);
        }
    }
    CP_WAIT(0);
    __syncthreads();

    // acc0 = rows [rowt*32 .. +16), acc1 = rows [rowt*32+16 .. +32), cols nq*64 + tl*8
    float acc0[8][4], acc1[8][4];
#pragma unroll
    for (int t = 0; t < 8; t++) {
        acc0[t][0]=acc0[t][1]=acc0[t][2]=acc0[t][3]=0.f;
        acc1[t][0]=acc1[t][1]=acc1[t][2]=acc1[t][3]=0.f;
    }

    const int rbase = rowt * 32 + (lane >> 2);

    // ---- layer 1: K=128, 8 ksteps, 2-term (A * (Wh + Wl)) ----
    {
        const uint32_t* Aw = (const uint32_t*)(smem + A1S);
#pragma unroll 1
        for (int ks = 0; ks < 8; ks++) {
            int kp = ks * 8 + (lane & 3);
            uint32_t a0[4], a1[4];
            a0[0] = Aw[rbase * 68 + kp];            a0[1] = Aw[(rbase + 8) * 68 + kp];
            a0[2] = Aw[rbase * 68 + kp + 4];        a0[3] = Aw[(rbase + 8) * 68 + kp + 4];
            a1[0] = Aw[(rbase + 16) * 68 + kp];     a1[1] = Aw[(rbase + 24) * 68 + kp];
            a1[2] = Aw[(rbase + 16) * 68 + kp + 4]; a1[3] = Aw[(rbase + 24) * 68 + kp + 4];
#pragma unroll
            for (int tl = 0; tl < 8; tl++) {
                int nt = nq * 8 + tl;
                uint2 bh = *(const uint2*)(smem + B1HI + (size_t)((nt * 8 + ks) * 32 + lane) * 8);
                uint2 bl = *(const uint2*)(smem + B1LO + (size_t)((nt * 8 + ks) * 32 + lane) * 8);
                mma_f16(acc0[tl], a0, (const uint32_t*)&bh);
                mma_f16(acc0[tl], a0, (const uint32_t*)&bl);
                mma_f16(acc1[tl], a1, (const uint32_t*)&bh);
                mma_f16(acc1[tl], a1, (const uint32_t*)&bl);
            }
        }
    }

    // rows owned by this thread
    const int r0 = rbase, r1 = rbase + 8, r2 = rbase + 16, r3 = rbase + 24;
    const float* b1s  = (const float*)(smem + OFF_B1S);
    const float* g1s  = (const float*)(smem + OFF_G1S);
    const float* be1s = (const float*)(smem + OFF_BE1S);
    float2* lnex = (float2*)(smem + OFF_LNEX);

    // ---- epilogue 1: bias + partial LN stats (per col-quarter) ----
    {
        float sa=0.f,s2a=0.f, sb=0.f,s2b=0.f, sc=0.f,s2c=0.f, sd=0.f,s2d=0.f;
#pragma unroll
        for (int tl = 0; tl < 8; tl++) {
            int c0 = nq * 64 + tl * 8 + (lane & 3) * 2;
            float bb0 = b1s[c0], bb1 = b1s[c0 + 1];
            acc0[tl][0] += bb0; acc0[tl][1] += bb1; acc0[tl][2] += bb0; acc0[tl][3] += bb1;
            acc1[tl][0] += bb0; acc1[tl][1] += bb1; acc1[tl][2] += bb0; acc1[tl][3] += bb1;
            sa += acc0[tl][0] + acc0[tl][1]; s2a += acc0[tl][0]*acc0[tl][0] + acc0[tl][1]*acc0[tl][1];
            sb += acc0[tl][2] + acc0[tl][3]; s2b += acc0[tl][2]*acc0[tl][2] + acc0[tl][3]*acc0[tl][3];
            sc += acc1[tl][0] + acc1[tl][1]; s2c += acc1[tl][0]*acc1[tl][0] + acc1[tl][1]*acc1[tl][1];
            sd += acc1[tl][2] + acc1[tl][3]; s2d += acc1[tl][2]*acc1[tl][2] + acc1[tl][3]*acc1[tl][3];
        }
#pragma unroll
        for (int o = 1; o <= 2; o <<= 1) {
            sa += __shfl_xor_sync(0xffffffffu, sa, o);  s2a += __shfl_xor_sync(0xffffffffu, s2a, o);
            sb += __shfl_xor_sync(0xffffffffu, sb, o);  s2b += __shfl_xor_sync(0xffffffffu, s2b, o);
            sc += __shfl_xor_sync(0xffffffffu, sc, o);  s2c += __shfl_xor_sync(0xffffffffu, s2c, o);
            sd += __shfl_xor_sync(0xffffffffu, sd, o);  s2d += __shfl_xor_sync(0xffffffffu, s2d, o);
        }
        if ((lane & 3) == 0) {
            lnex[r0 * 4 + nq] = make_float2(sa, s2a);
            lnex[r1 * 4 + nq] = make_float2(sb, s2b);
            lnex[r2 * 4 + nq] = make_float2(sc, s2c);
            lnex[r3 * 4 + nq] = make_float2(sd, s2d);
        }
    }
    __syncthreads();   // layer-1 mma + stats done everywhere; A1/B1 now dead

    // prefetch W2 chunk 0 into buf0
    {
        uint32_t d0 = (uint32_t)__cvta_generic_to_shared(smem + B2BUF0);
#pragma unroll
        for (int i = 0; i < 2; i++) {
            cp16(d0 + (tid + i * NTHR) * 16,           (const char*)g_W2hi + (tid + i * NTHR) * 16);
            cp16(d0 + 16384 + (tid + i * NTHR) * 16,   (const char*)g_W2lo + (tid + i * NTHR) * 16);
        }
        CP_COMMIT();
    }

    // ---- LN1 transform + ReLU -> A2 fp16 (stride 132 words) ----
    {
        float mu[4], rs[4];
        int rr[4] = {r0, r1, r2, r3};
#pragma unroll
        for (int k = 0; k < 4; k++) {
            float2 q0 = lnex[rr[k] * 4 + 0], q1 = lnex[rr[k] * 4 + 1];
            float2 q2 = lnex[rr[k] * 4 + 2], q3 = lnex[rr[k] * 4 + 3];
            float s  = q0.x + q1.x + q2.x + q3.x;
            float s2 = q0.y + q1.y + q2.y + q3.y;
            mu[k] = s * (1.f / HH);
            rs[k] = rsqrtf(s2 * (1.f / HH) - mu[k] * mu[k] + EPSLN);
        }
        uint32_t* A2w = (uint32_t*)(smem + A2S);
#pragma unroll
        for (int tl = 0; tl < 8; tl++) {
            int c0 = nq * 64 + tl * 8 + (lane & 3) * 2;
            float ga = g1s[c0], gb = g1s[c0 + 1], ba = be1s[c0], bb = be1s[c0 + 1];
            int w = c0 >> 1;
            A2w[r0 * 132 + w] = pack_f16x2(
                fmaxf((acc0[tl][0] - mu[0]) * rs[0] * ga + ba, 0.f),
                fmaxf((acc0[tl][1] - mu[0]) * rs[0] * gb + bb, 0.f));
            A2w[r1 * 132 + w] = pack_f16x2(
                fmaxf((acc0[tl][2] - mu[1]) * rs[1] * ga + ba, 0.f),
                fmaxf((acc0[tl][3] - mu[1]) * rs[1] * gb + bb, 0.f));
            A2w[r2 * 132 + w] = pack_f16x2(
                fmaxf((acc1[tl][0] - mu[2]) * rs[2] * ga + ba, 0.f),
                fmaxf((acc1[tl][1] - mu[2]) * rs[2] * gb + bb, 0.f));
            A2w[r3 * 132 + w] = pack_f16x2(
                fmaxf((acc1[tl][2] - mu[3]) * rs[3] * ga + ba, 0.f),
                fmaxf((acc1[tl][3] - mu[3]) * rs[3] * gb + bb, 0.f));
        }
    }

#pragma unroll
    for (int t = 0; t < 8; t++) {
        acc0[t][0]=acc0[t][1]=acc0[t][2]=acc0[t][3]=0.f;
        acc1[t][0]=acc1[t][1]=acc1[t][2]=acc1[t][3]=0.f;
    }

    // ---- layer 2: K=256 in 8 chunks of 32, double-buffered cp.async ----
    {
        const uint32_t* Aw = (const uint32_t*)(smem + A2S);
#pragma unroll 1
        for (int kc = 0; kc < 8; kc++) {
            __syncthreads();   // prior reads of the buffer being overwritten are done
            if (kc < 7) {
                uint32_t d = (uint32_t)__cvta_generic_to_shared(
                    smem + (((kc + 1) & 1) ? B2BUF1 : B2BUF0));
                const char* sh = (const char*)g_W2hi + (kc + 1) * 16384;
                const char* sl = (const char*)g_W2lo + (kc + 1) * 16384;
#pragma unroll
                for (int i = 0; i < 2; i++) {
                    cp16(d + (tid + i * NTHR) * 16,         sh + (tid + i * NTHR) * 16);
                    cp16(d + 16384 + (tid + i * NTHR) * 16, sl + (tid + i * NTHR) * 16);
                }
                CP_COMMIT();
                CP_WAIT(1);    // chunk kc has landed
            } else {
                CP_WAIT(0);
            }
            __syncthreads();   // chunk kc visible to all warps
            const char* buf = smem + ((kc & 1) ? B2BUF1 : B2BUF0);
#pragma unroll
            for (int ks = 0; ks < 2; ks++) {
                int kp = kc * 16 + ks * 8 + (lane & 3);
                uint32_t a0[4], a1[4];
                a0[0] = Aw[rbase * 132 + kp];            a0[1] = Aw[(rbase + 8) * 132 + kp];
                a0[2] = Aw[rbase * 132 + kp + 4];        a0[3] = Aw[(rbase + 8) * 132 + kp + 4];
                a1[0] = Aw[(rbase + 16) * 132 + kp];     a1[1] = Aw[(rbase + 24) * 132 + kp];
                a1[2] = Aw[(rbase + 16) * 132 + kp + 4]; a1[3] = Aw[(rbase + 24) * 132 + kp + 4];
#pragma unroll
                for (int tl = 0; tl < 8; tl++) {
                    int nt = nq * 8 + tl;
                    uint2 bh = *(const uint2*)(buf + (size_t)((nt * 2 + ks) * 32 + lane) * 8);
                    uint2 bl = *(const uint2*)(buf + 16384 + (size_t)((nt * 2 + ks) * 32 + lane) * 8);
                    mma_f16(acc0[tl], a0, (const uint32_t*)&bh);
                    mma_f16(acc0[tl], a0, (const uint32_t*)&bl);
                    mma_f16(acc1[tl], a1, (const uint32_t*)&bh);
                    mma_f16(acc1[tl], a1, (const uint32_t*)&bl);
                }
            }
        }
    }

    // ---- epilogue 2: bias + partial LN stats ----
    const float* b2s  = (const float*)(smem + OFF_B2S);
    const float* g2s  = (const float*)(smem + OFF_G2S);
    const float* be2s = (const float*)(smem + OFF_BE2S);
    const float* w3s  = (const float*)(smem + OFF_W3S);
    {
        float sa=0.f,s2a=0.f, sb=0.f,s2b=0.f, sc=0.f,s2c=0.f, sd=0.f,s2d=0.f;
#pragma unroll
        for (int tl = 0; tl < 8; tl++) {
            int c0 = nq * 64 + tl * 8 + (lane & 3) * 2;
            float bb0 = b2s[c0], bb1 = b2s[c0 + 1];
            acc0[tl][0] += bb0; acc0[tl][1] += bb1; acc0[tl][2] += bb0; acc0[tl][3] += bb1;
            acc1[tl][0] += bb0; acc1[tl][1] += bb1; acc1[tl][2] += bb0; acc1[tl][3] += bb1;
            sa += acc0[tl][0] + acc0[tl][1]; s2a += acc0[tl][0]*acc0[tl][0] + acc0[tl][1]*acc0[tl][1];
            sb += acc0[tl][2] + acc0[tl][3]; s2b += acc0[tl][2]*acc0[tl][2] + acc0[tl][3]*acc0[tl][3];
            sc += acc1[tl][0] + acc1[tl][1]; s2c += acc1[tl][0]*acc1[tl][0] + acc1[tl][1]*acc1[tl][1];
            sd += acc1[tl][2] + acc1[tl][3]; s2d += acc1[tl][2]*acc1[tl][2] + acc1[tl][3]*acc1[tl][3];
        }
#pragma unroll
        for (int o = 1; o <= 2; o <<= 1) {
            sa += __shfl_xor_sync(0xffffffffu, sa, o);  s2a += __shfl_xor_sync(0xffffffffu, s2a, o);
            sb += __shfl_xor_sync(0xffffffffu, sb, o);  s2b += __shfl_xor_sync(0xffffffffu, s2b, o);
            sc += __shfl_xor_sync(0xffffffffu, sc, o);  s2c += __shfl_xor_sync(0xffffffffu, s2c, o);
            sd += __shfl_xor_sync(0xffffffffu, sd, o);  s2d += __shfl_xor_sync(0xffffffffu, s2d, o);
        }
        if ((lane & 3) == 0) {
            lnex[r0 * 4 + nq] = make_float2(sa, s2a);
            lnex[r1 * 4 + nq] = make_float2(sb, s2b);
            lnex[r2 * 4 + nq] = make_float2(sc, s2c);
            lnex[r3 * 4 + nq] = make_float2(sd, s2d);
        }
    }
    __syncthreads();
    // ---- LN2 + ReLU + dot W3 partials ----
    {
        float mu[4], rs[4];
        int rr[4] = {r0, r1, r2, r3};
#pragma unroll
        for (int k = 0; k < 4; k++) {
            float2 q0 = lnex[rr[k] * 4 + 0], q1 = lnex[rr[k] * 4 + 1];
            float2 q2 = lnex[rr[k] * 4 + 2], q3 = lnex[rr[k] * 4 + 3];
            float s  = q0.x + q1.x + q2.x + q3.x;
            float s2 = q0.y + q1.y + q2.y + q3.y;
            mu[k] = s * (1.f / HH);
            rs[k] = rsqrtf(s2 * (1.f / HH) - mu[k] * mu[k] + EPSLN);
        }
        float pa = 0.f, pb = 0.f, pc = 0.f, pd = 0.f;
#pragma unroll
        for (int tl = 0; tl < 8; tl++) {
            int c0 = nq * 64 + tl * 8 + (lane & 3) * 2;
            float ga = g2s[c0], gb = g2s[c0 + 1], ba = be2s[c0], bb = be2s[c0 + 1];
            float w0 = w3s[c0], w1 = w3s[c0 + 1];
            pa = fmaf(fmaxf((acc0[tl][0] - mu[0]) * rs[0] * ga + ba, 0.f), w0, pa);
            pa = fmaf(fmaxf((acc0[tl][1] - mu[0]) * rs[0] * gb + bb, 0.f), w1, pa);
            pb = fmaf(fmaxf((acc0[tl][2] - mu[1]) * rs[1] * ga + ba, 0.f), w0, pb);
            pb = fmaf(fmaxf((acc0[tl][3] - mu[1]) * rs[1] * gb + bb, 0.f), w1, pb);
            pc = fmaf(fmaxf((acc1[tl][0] - mu[2]) * rs[2] * ga + ba, 0.f), w0, pc);
            pc = fmaf(fmaxf((acc1[tl][1] - mu[2]) * rs[2] * gb + bb, 0.f), w1, pc);
            pd = fmaf(fmaxf((acc1[tl][2] - mu[3]) * rs[3] * ga + ba, 0.f), w0, pd);
            pd = fmaf(fmaxf((acc1[tl][3] - mu[3]) * rs[3] * gb + bb, 0.f), w1, pd);
        }
#pragma unroll
        for (int o = 1; o <= 2; o <<= 1) {
            pa += __shfl_xor_sync(0xffffffffu, pa, o);
            pb += __shfl_xor_sync(0xffffffffu, pb, o);
            pc += __shfl_xor_sync(0xffffffffu, pc, o);
            pd += __shfl_xor_sync(0xffffffffu, pd, o);
        }
        float* pex = (float*)(smem + OFF_PEX);
        if ((lane & 3) == 0) {
            pex[r0 * 4 + nq] = pa;
            pex[r1 * 4 + nq] = pb;
            pex[r2 * 4 + nq] = pc;
            pex[r3 * 4 + nq] = pd;
        }
    }
    __syncthreads();
    if (tid < TE) {
        float* pex = (float*)(smem + OFF_PEX);
        float p = pex[tid * 4] + pex[tid * 4 + 1] + pex[tid * 4 + 2] + pex[tid * 4 + 3] + b3[0];
        int eg = e0 + tid;
        if (eg < E) out[eg] = 1.f / (1.f + expf(-p));
    }
}

extern "C" void kernel_launch(void* const* d_in, const int* in_sizes, int n_in,
                              void* d_out, int out_size)
{
    const float* h   = (const float*)d_in[0];
    const int*   src = (const int*)d_in[1];
    const int*   dst = (const int*)d_in[2];
    const float* W1 = (const float*)d_in[3];  const float* b1 = (const float*)d_in[4];
    const float* g1 = (const float*)d_in[5];  const float* be1 = (const float*)d_in[6];
    const float* W2 = (const float*)d_in[7];  const float* b2 = (const float*)d_in[8];
    const float* g2 = (const float*)d_in[9];  const float* be2 = (const float*)d_in[10];
    const float* W3 = (const float*)d_in[11]; const float* b3 = (const float*)d_in[12];

    int E  = in_sizes[1];
    int Nn = in_sizes[0] / DD;

    prep_kernel<<<(8192 + 16384 + 255) / 256, 256>>>(W1, W2);

    cudaFuncSetAttribute(mlp_mma_kernel,
                         cudaFuncAttributeMaxDynamicSharedMemorySize, SMEM_BYTES);
    int grid = (E + TE - 1) / TE;
    mlp_mma_kernel<<<grid, NTHR, SMEM_BYTES>>>(
        h, src, dst, b1, g1, be1, b2, g2, be2, W3, b3,
        (float*)d_out, E, Nn);
}

// round 8
// speedup vs baseline: 6.1232x; 1.3633x over previous
#include <cuda_runtime.h>
#include <cuda_fp16.h>
#include <math.h>
#include <stdint.h>

#define NTHR 512
#define TE   128
#define DD   128
#define HH   256
#define EPSLN 1e-5f

// ---------------- smem layout (byte offsets) ----------------
#define OFF_B1S   0
#define OFF_G1S   1024
#define OFF_BE1S  2048
#define OFF_B2S   3072
#define OFF_G2S   4096
#define OFF_BE2S  5120
#define OFF_W3S   6144
#define OFF_LNEX  7168      // 128 rows x 4 quarters x float2 = 4096
#define OFF_PEX   11264     // 128 rows x 4 quarters x float = 2048
#define TILES     13312
// phase 1: A1 (128x128 fp16, row stride 68 words) ; B1 blob
#define A1S   (TILES)                  // 34816
#define B1S   (TILES + 34816)          // 65536 -> ends TILES+100352
// phase 2 (alias): A2 (128x256 fp16, row stride 132 words) ; B2 double buffer
#define A2S    (TILES)                 // 67584
#define B2BUF0 (TILES + 67584)         // 16384
#define B2BUF1 (TILES + 83968)         // 16384 -> ends TILES+100352
#define SMEM_BYTES (TILES + 100352)    // 113664

// fragment-ordered fp16 weight blobs:
// W1 blob slot = ((ntile*8 + kstep)*32 + lane) -> 8 bytes
//   {W[n][k0],W[n][k0+1], W[n][k0+8],W[n][k0+9]}, n = ntile*8 + lane/4, k0 = kstep*16 + (lane%4)*2
__device__ __align__(16) unsigned char g_W1f[65536];
// W2 blob: [kchunk 8][ntile 32][kstep 2][lane 32] x 8B   (chunk = K 32)
__device__ __align__(16) unsigned char g_W2f[131072];

__device__ __forceinline__ uint32_t pack_f16x2(float a, float b) {
    __half2 h = __floats2half2_rn(a, b);
    return *reinterpret_cast<uint32_t*>(&h);
}

__device__ __forceinline__ void mma_f16(float d[4], const uint32_t a[4], const uint32_t b[2]) {
    asm volatile(
        "mma.sync.aligned.m16n8k16.row.col.f32.f16.f16.f32 "
        "{%0,%1,%2,%3}, {%4,%5,%6,%7}, {%8,%9}, {%0,%1,%2,%3};"
        : "+f"(d[0]), "+f"(d[1]), "+f"(d[2]), "+f"(d[3])
        : "r"(a[0]), "r"(a[1]), "r"(a[2]), "r"(a[3]), "r"(b[0]), "r"(b[1]));
}

__device__ __forceinline__ void cp16(uint32_t dst_smem, const void* gsrc) {
    asm volatile("cp.async.cg.shared.global [%0], [%1], 16;" :: "r"(dst_smem), "l"(gsrc));
}
#define CP_COMMIT() asm volatile("cp.async.commit_group;" ::: "memory")
#define CP_WAIT(N)  asm volatile("cp.async.wait_group %0;" :: "n"(N) : "memory")

// ---------------- prep: repack weights into fragment-ordered fp16 blobs ----------------
__global__ void prep_kernel(const float* __restrict__ W1, const float* __restrict__ W2) {
    int i = blockIdx.x * blockDim.x + threadIdx.x;
    if (i < 8192) {                                    // W1 [256n][128k], 32 nt x 8 ks
        int nt = i >> 8, ks = (i >> 5) & 7, lane = i & 31;
        int n = nt * 8 + (lane >> 2);
        int k0 = ks * 16 + (lane & 3) * 2;
        const float* w = W1 + n * 128 + k0;
        ((uint2*)g_W1f)[i] = make_uint2(pack_f16x2(w[0], w[1]), pack_f16x2(w[8], w[9]));
    } else if (i < 8192 + 16384) {                     // W2 [256n][256k], 8 kc x 32 nt x 2 ks
        int j = i - 8192;
        int kc = j >> 11, nt = (j >> 6) & 31, ks = (j >> 5) & 1, lane = j & 31;
        int n = nt * 8 + (lane >> 2);
        int k0 = kc * 32 + ks * 16 + (lane & 3) * 2;
        const float* w = W2 + n * 256 + k0;
        ((uint2*)g_W2f)[j] = make_uint2(pack_f16x2(w[0], w[1]), pack_f16x2(w[8], w[9]));
    }
}

// ---------------- main ----------------
__global__ void __launch_bounds__(NTHR, 1)
mlp_mma_kernel(const float* __restrict__ h,
               const int* __restrict__ src, const int* __restrict__ dst,
               const float* __restrict__ b1, const float* __restrict__ g1, const float* __restrict__ be1,
               const float* __restrict__ b2, const float* __restrict__ g2, const float* __restrict__ be2,
               const float* __restrict__ W3, const float* __restrict__ b3,
               float* __restrict__ out, int E, int Nn)
{
    extern __shared__ __align__(16) char smem[];
    const int tid   = threadIdx.x;
    const int wid   = tid >> 5;
    const int lane  = tid & 31;
    const int rowt  = wid & 3;          // row group: rows [rowt*32, rowt*32+32)
    const int nq    = wid >> 2;         // col quarter: cols [nq*64, nq*64+64)
    const int e0    = blockIdx.x * TE;

    // --- async-stage B1 blob (65536 B) ---
    {
        uint32_t dh = (uint32_t)__cvta_generic_to_shared(smem + B1S);
#pragma unroll
        for (int i = 0; i < 8; i++)
            cp16(dh + (tid + i * NTHR) * 16, (const char*)g_W1f + (tid + i * NTHR) * 16);
        CP_COMMIT();
    }

    // --- params ---
    if (tid < HH) {
        ((float*)(smem + OFF_B1S))[tid]  = b1[tid];
        ((float*)(smem + OFF_G1S))[tid]  = g1[tid];
        ((float*)(smem + OFF_BE1S))[tid] = be1[tid];
        ((float*)(smem + OFF_B2S))[tid]  = b2[tid];
        ((float*)(smem + OFF_G2S))[tid]  = g2[tid];
        ((float*)(smem + OFF_BE2S))[tid] = be2[tid];
        ((float*)(smem + OFF_W3S))[tid]  = W3[tid];
    }

    // --- gather x = h[src]*h[dst] -> fp16, A1 row-major (stride 68 words) ---
    {
        int row = tid >> 2, q = tid & 3;
        int eg = e0 + row;
        int si = 0, di = 0;
        if (eg < E) { si = src[eg]; di = dst[eg]; }
        if ((unsigned)si >= (unsigned)Nn) si = 0;
        if ((unsigned)di >= (unsigned)Nn) di = 0;
        const float4* ps = (const float4*)(h + (size_t)si * DD) + q * 8;
        const float4* pd = (const float4*)(h + (size_t)di * DD) + q * 8;
        uint32_t* oh = (uint32_t*)(smem + A1S) + row * 68 + q * 16;
#pragma unroll
        for (int i = 0; i < 8; i++) {
            float4 a = ps[i], b = pd[i];
            oh[i * 2]     = pack_f16x2(a.x * b.x, a.y * b.y);
            oh[i * 2 + 1] = pack_f16x2(a.z * b.z, a.w * b.w);
        }
    }
    CP_WAIT(0);
    __syncthreads();

    // acc0 = rows [rowt*32 .. +16), acc1 = rows [rowt*32+16 .. +32), cols nq*64 + tl*8
    float acc0[8][4], acc1[8][4];
#pragma unroll
    for (int t = 0; t < 8; t++) {
        acc0[t][0]=acc0[t][1]=acc0[t][2]=acc0[t][3]=0.f;
        acc1[t][0]=acc1[t][1]=acc1[t][2]=acc1[t][3]=0.f;
    }

    const int rbase = rowt * 32 + (lane >> 2);

    // ---- layer 1: K=128, 8 ksteps, plain fp16 ----
    {
        const uint32_t* Aw = (const uint32_t*)(smem + A1S);
#pragma unroll 1
        for (int ks = 0; ks < 8; ks++) {
            int kp = ks * 8 + (lane & 3);
            uint32_t a0[4], a1[4];
            a0[0] = Aw[rbase * 68 + kp];            a0[1] = Aw[(rbase + 8) * 68 + kp];
            a0[2] = Aw[rbase * 68 + kp + 4];        a0[3] = Aw[(rbase + 8) * 68 + kp + 4];
            a1[0] = Aw[(rbase + 16) * 68 + kp];     a1[1] = Aw[(rbase + 24) * 68 + kp];
            a1[2] = Aw[(rbase + 16) * 68 + kp + 4]; a1[3] = Aw[(rbase + 24) * 68 + kp + 4];
#pragma unroll
            for (int tl = 0; tl < 8; tl++) {
                int nt = nq * 8 + tl;
                uint2 bh = *(const uint2*)(smem + B1S + (size_t)((nt * 8 + ks) * 32 + lane) * 8);
                mma_f16(acc0[tl], a0, (const uint32_t*)&bh);
                mma_f16(acc1[tl], a1, (const uint32_t*)&bh);
            }
        }
    }

    // rows owned by this thread
    const int r0 = rbase, r1 = rbase + 8, r2 = rbase + 16, r3 = rbase + 24;
    const float* b1s  = (const float*)(smem + OFF_B1S);
    const float* g1s  = (const float*)(smem + OFF_G1S);
    const float* be1s = (const float*)(smem + OFF_BE1S);
    float2* lnex = (float2*)(smem + OFF_LNEX);

    // ---- epilogue 1: bias + partial LN stats (per col-quarter) ----
    {
        float sa=0.f,s2a=0.f, sb=0.f,s2b=0.f, sc=0.f,s2c=0.f, sd=0.f,s2d=0.f;
#pragma unroll
        for (int tl = 0; tl < 8; tl++) {
            int c0 = nq * 64 + tl * 8 + (lane & 3) * 2;
            float bb0 = b1s[c0], bb1 = b1s[c0 + 1];
            acc0[tl][0] += bb0; acc0[tl][1] += bb1; acc0[tl][2] += bb0; acc0[tl][3] += bb1;
            acc1[tl][0] += bb0; acc1[tl][1] += bb1; acc1[tl][2] += bb0; acc1[tl][3] += bb1;
            sa += acc0[tl][0] + acc0[tl][1]; s2a += acc0[tl][0]*acc0[tl][0] + acc0[tl][1]*acc0[tl][1];
            sb += acc0[tl][2] + acc0[tl][3]; s2b += acc0[tl][2]*acc0[tl][2] + acc0[tl][3]*acc0[tl][3];
            sc += acc1[tl][0] + acc1[tl][1]; s2c += acc1[tl][0]*acc1[tl][0] + acc1[tl][1]*acc1[tl][1];
            sd += acc1[tl][2] + acc1[tl][3]; s2d += acc1[tl][2]*acc1[tl][2] + acc1[tl][3]*acc1[tl][3];
        }
#pragma unroll
        for (int o = 1; o <= 2; o <<= 1) {
            sa += __shfl_xor_sync(0xffffffffu, sa, o);  s2a += __shfl_xor_sync(0xffffffffu, s2a, o);
            sb += __shfl_xor_sync(0xffffffffu, sb, o);  s2b += __shfl_xor_sync(0xffffffffu, s2b, o);
            sc += __shfl_xor_sync(0xffffffffu, sc, o);  s2c += __shfl_xor_sync(0xffffffffu, s2c, o);
            sd += __shfl_xor_sync(0xffffffffu, sd, o);  s2d += __shfl_xor_sync(0xffffffffu, s2d, o);
        }
        if ((lane & 3) == 0) {
            lnex[r0 * 4 + nq] = make_float2(sa, s2a);
            lnex[r1 * 4 + nq] = make_float2(sb, s2b);
            lnex[r2 * 4 + nq] = make_float2(sc, s2c);
            lnex[r3 * 4 + nq] = make_float2(sd, s2d);
        }
    }
    __syncthreads();   // layer-1 mma + stats done everywhere; A1/B1 now dead

    // prefetch W2 chunk 0 into buf0
    {
        uint32_t d0 = (uint32_t)__cvta_generic_to_shared(smem + B2BUF0);
#pragma unroll
        for (int i = 0; i < 2; i++)
            cp16(d0 + (tid + i * NTHR) * 16, (const char*)g_W2f + (tid + i * NTHR) * 16);
        CP_COMMIT();
    }

    // ---- LN1 transform + ReLU -> A2 fp16 (stride 132 words) ----
    {
        float mu[4], rs[4];
        int rr[4] = {r0, r1, r2, r3};
#pragma unroll
        for (int k = 0; k < 4; k++) {
            float2 q0 = lnex[rr[k] * 4 + 0], q1 = lnex[rr[k] * 4 + 1];
            float2 q2 = lnex[rr[k] * 4 + 2], q3 = lnex[rr[k] * 4 + 3];
            float s  = q0.x + q1.x + q2.x + q3.x;
            float s2 = q0.y + q1.y + q2.y + q3.y;
            mu[k] = s * (1.f / HH);
            rs[k] = rsqrtf(s2 * (1.f / HH) - mu[k] * mu[k] + EPSLN);
        }
        uint32_t* A2w = (uint32_t*)(smem + A2S);
#pragma unroll
        for (int tl = 0; tl < 8; tl++) {
            int c0 = nq * 64 + tl * 8 + (lane & 3) * 2;
            float ga = g1s[c0], gb = g1s[c0 + 1], ba = be1s[c0], bb = be1s[c0 + 1];
            int w = c0 >> 1;
            A2w[r0 * 132 + w] = pack_f16x2(
                fmaxf((acc0[tl][0] - mu[0]) * rs[0] * ga + ba, 0.f),
                fmaxf((acc0[tl][1] - mu[0]) * rs[0] * gb + bb, 0.f));
            A2w[r1 * 132 + w] = pack_f16x2(
                fmaxf((acc0[tl][2] - mu[1]) * rs[1] * ga + ba, 0.f),
                fmaxf((acc0[tl][3] - mu[1]) * rs[1] * gb + bb, 0.f));
            A2w[r2 * 132 + w] = pack_f16x2(
                fmaxf((acc1[tl][0] - mu[2]) * rs[2] * ga + ba, 0.f),
                fmaxf((acc1[tl][1] - mu[2]) * rs[2] * gb + bb, 0.f));
            A2w[r3 * 132 + w] = pack_f16x2(
                fmaxf((acc1[tl][2] - mu[3]) * rs[3] * ga + ba, 0.f),
                fmaxf((acc1[tl][3] - mu[3]) * rs[3] * gb + bb, 0.f));
        }
    }

#pragma unroll
    for (int t = 0; t < 8; t++) {
        acc0[t][0]=acc0[t][1]=acc0[t][2]=acc0[t][3]=0.f;
        acc1[t][0]=acc1[t][1]=acc1[t][2]=acc1[t][3]=0.f;
    }

    // ---- layer 2: K=256 in 8 chunks of 32, double-buffered cp.async ----
    {
        const uint32_t* Aw = (const uint32_t*)(smem + A2S);
#pragma unroll 1
        for (int kc = 0; kc < 8; kc++) {
            __syncthreads();   // prior reads of the buffer being overwritten are done
            if (kc < 7) {
                uint32_t d = (uint32_t)__cvta_generic_to_shared(
                    smem + (((kc + 1) & 1) ? B2BUF1 : B2BUF0));
                const char* sh = (const char*)g_W2f + (kc + 1) * 16384;
#pragma unroll
                for (int i = 0; i < 2; i++)
                    cp16(d + (tid + i * NTHR) * 16, sh + (tid + i * NTHR) * 16);
                CP_COMMIT();
                CP_WAIT(1);    // chunk kc has landed
            } else {
                CP_WAIT(0);
            }
            __syncthreads();   // chunk kc visible to all warps
            const char* buf = smem + ((kc & 1) ? B2BUF1 : B2BUF0);
#pragma unroll
            for (int ks = 0; ks < 2; ks++) {
                int kp = kc * 16 + ks * 8 + (lane & 3);
                uint32_t a0[4], a1[4];
                a0[0] = Aw[rbase * 132 + kp];            a0[1] = Aw[(rbase + 8) * 132 + kp];
                a0[2] = Aw[rbase * 132 + kp + 4];        a0[3] = Aw[(rbase + 8) * 132 + kp + 4];
                a1[0] = Aw[(rbase + 16) * 132 + kp];     a1[1] = Aw[(rbase + 24) * 132 + kp];
                a1[2] = Aw[(rbase + 16) * 132 + kp + 4]; a1[3] = Aw[(rbase + 24) * 132 + kp + 4];
#pragma unroll
                for (int tl = 0; tl < 8; tl++) {
                    int nt = nq * 8 + tl;
                    uint2 bh = *(const uint2*)(buf + (size_t)((nt * 2 + ks) * 32 + lane) * 8);
                    mma_f16(acc0[tl], a0, (const uint32_t*)&bh);
                    mma_f16(acc1[tl], a1, (const uint32_t*)&bh);
                }
            }
        }
    }

    // ---- epilogue 2: bias + partial LN stats ----
    const float* b2s  = (const float*)(smem + OFF_B2S);
    const float* g2s  = (const float*)(smem + OFF_G2S);
    const float* be2s = (const float*)(smem + OFF_BE2S);
    const float* w3s  = (const float*)(smem + OFF_W3S);
    {
        float sa=0.f,s2a=0.f, sb=0.f,s2b=0.f, sc=0.f,s2c=0.f, sd=0.f,s2d=0.f;
#pragma unroll
        for (int tl = 0; tl < 8; tl++) {
            int c0 = nq * 64 + tl * 8 + (lane & 3) * 2;
            float bb0 = b2s[c0], bb1 = b2s[c0 + 1];
            acc0[tl][0] += bb0; acc0[tl][1] += bb1; acc0[tl][2] += bb0; acc0[tl][3] += bb1;
            acc1[tl][0] += bb0; acc1[tl][1] += bb1; acc1[tl][2] += bb0; acc1[tl][3] += bb1;
            sa += acc0[tl][0] + acc0[tl][1]; s2a += acc0[tl][0]*acc0[tl][0] + acc0[tl][1]*acc0[tl][1];
            sb += acc0[tl][2] + acc0[tl][3]; s2b += acc0[tl][2]*acc0[tl][2] + acc0[tl][3]*acc0[tl][3];
            sc += acc1[tl][0] + acc1[tl][1]; s2c += acc1[tl][0]*acc1[tl][0] + acc1[tl][1]*acc1[tl][1];
            sd += acc1[tl][2] + acc1[tl][3]; s2d += acc1[tl][2]*acc1[tl][2] + acc1[tl][3]*acc1[tl][3];
        }
#pragma unroll
        for (int o = 1; o <= 2; o <<= 1) {
            sa += __shfl_xor_sync(0xffffffffu, sa, o);  s2a += __shfl_xor_sync(0xffffffffu, s2a, o);
            sb += __shfl_xor_sync(0xffffffffu, sb, o);  s2b += __shfl_xor_sync(0xffffffffu, s2b, o);
            sc += __shfl_xor_sync(0xffffffffu, sc, o);  s2c += __shfl_xor_sync(0xffffffffu, s2c, o);
            sd += __shfl_xor_sync(0xffffffffu, sd, o);  s2d += __shfl_xor_sync(0xffffffffu, s2d, o);
        }
        if ((lane & 3) == 0) {
            lnex[r0 * 4 + nq] = make_float2(sa, s2a);
            lnex[r1 * 4 + nq] = make_float2(sb, s2b);
            lnex[r2 * 4 + nq] = make_float2(sc, s2c);
            lnex[r3 * 4 + nq] = make_float2(sd, s2d);
        }
    }
    __syncthreads();
    // ---- LN2 + ReLU + dot W3 partials ----
    {
        float mu[4], rs[4];
        int rr[4] = {r0, r1, r2, r3};
#pragma unroll
        for (int k = 0; k < 4; k++) {
            float2 q0 = lnex[rr[k] * 4 + 0], q1 = lnex[rr[k] * 4 + 1];
            float2 q2 = lnex[rr[k] * 4 + 2], q3 = lnex[rr[k] * 4 + 3];
            float s  = q0.x + q1.x + q2.x + q3.x;
            float s2 = q0.y + q1.y + q2.y + q3.y;
            mu[k] = s * (1.f / HH);
            rs[k] = rsqrtf(s2 * (1.f / HH) - mu[k] * mu[k] + EPSLN);
        }
        float pa = 0.f, pb = 0.f, pc = 0.f, pd = 0.f;
#pragma unroll
        for (int tl = 0; tl < 8; tl++) {
            int c0 = nq * 64 + tl * 8 + (lane & 3) * 2;
            float ga = g2s[c0], gb = g2s[c0 + 1], ba = be2s[c0], bb = be2s[c0 + 1];
            float w0 = w3s[c0], w1 = w3s[c0 + 1];
            pa = fmaf(fmaxf((acc0[tl][0] - mu[0]) * rs[0] * ga + ba, 0.f), w0, pa);
            pa = fmaf(fmaxf((acc0[tl][1] - mu[0]) * rs[0] * gb + bb, 0.f), w1, pa);
            pb = fmaf(fmaxf((acc0[tl][2] - mu[1]) * rs[1] * ga + ba, 0.f), w0, pb);
            pb = fmaf(fmaxf((acc0[tl][3] - mu[1]) * rs[1] * gb + bb, 0.f), w1, pb);
            pc = fmaf(fmaxf((acc1[tl][0] - mu[2]) * rs[2] * ga + ba, 0.f), w0, pc);
            pc = fmaf(fmaxf((acc1[tl][1] - mu[2]) * rs[2] * gb + bb, 0.f), w1, pc);
            pd = fmaf(fmaxf((acc1[tl][2] - mu[3]) * rs[3] * ga + ba, 0.f), w0, pd);
            pd = fmaf(fmaxf((acc1[tl][3] - mu[3]) * rs[3] * gb + bb, 0.f), w1, pd);
        }
#pragma unroll
        for (int o = 1; o <= 2; o <<= 1) {
            pa += __shfl_xor_sync(0xffffffffu, pa, o);
            pb += __shfl_xor_sync(0xffffffffu, pb, o);
            pc += __shfl_xor_sync(0xffffffffu, pc, o);
            pd += __shfl_xor_sync(0xffffffffu, pd, o);
        }
        float* pex = (float*)(smem + OFF_PEX);
        if ((lane & 3) == 0) {
            pex[r0 * 4 + nq] = pa;
            pex[r1 * 4 + nq] = pb;
            pex[r2 * 4 + nq] = pc;
            pex[r3 * 4 + nq] = pd;
        }
    }
    __syncthreads();
    if (tid < TE) {
        float* pex = (float*)(smem + OFF_PEX);
        float p = pex[tid * 4] + pex[tid * 4 + 1] + pex[tid * 4 + 2] + pex[tid * 4 + 3] + b3[0];
        int eg = e0 + tid;
        if (eg < E) out[eg] = 1.f / (1.f + expf(-p));
    }
}

extern "C" void kernel_launch(void* const* d_in, const int* in_sizes, int n_in,
                              void* d_out, int out_size)
{
    const float* h   = (const float*)d_in[0];
    const int*   src = (const int*)d_in[1];
    const int*   dst = (const int*)d_in[2];
    const float* W1 = (const float*)d_in[3];  const float* b1 = (const float*)d_in[4];
    const float* g1 = (const float*)d_in[5];  const float* be1 = (const float*)d_in[6];
    const float* W2 = (const float*)d_in[7];  const float* b2 = (const float*)d_in[8];
    const float* g2 = (const float*)d_in[9];  const float* be2 = (const float*)d_in[10];
    const float* W3 = (const float*)d_in[11]; const float* b3 = (const float*)d_in[12];

    int E  = in_sizes[1];
    int Nn = in_sizes[0] / DD;

    prep_kernel<<<(8192 + 16384 + 255) / 256, 256>>>(W1, W2);

    cudaFuncSetAttribute(mlp_mma_kernel,
                         cudaFuncAttributeMaxDynamicSharedMemorySize, SMEM_BYTES);
    int grid = (E + TE - 1) / TE;
    mlp_mma_kernel<<<grid, NTHR, SMEM_BYTES>>>(
        h, src, dst, b1, g1, be1, b2, g2, be2, W3, b3,
        (float*)d_out, E, Nn);
}